// round 13
// baseline (speedup 1.0000x reference)
#include <cuda_runtime.h>
#include <cuda_fp16.h>
#include <cuda_bf16.h>
#include <cstdint>

// Problem constants
#define NNODE 1024
#define TSTEP 32
#define HDIM  256
#define PDIM  256
#define EDIM  512
#define DTR   16
#define SDIM  16
#define NT    (NNODE * TSTEP)   // 32768

#define SMEM_SWIZZLE_128B(byte_offset) \
    ((byte_offset) ^ (((byte_offset) >> 3) & 0x70))

typedef unsigned short ush;

// ===========================================================================
// Scratch (device globals)
// ===========================================================================
__device__ float g_pe    [NNODE * PDIM];
__device__ float g_pre1  [NNODE * HDIM];
__device__ float g_pebase[NNODE * HDIM];
__device__ float g_M1c   [HDIM * HDIM];
__device__ float g_M2c   [HDIM * HDIM];
__device__ float g_cvec1 [HDIM];
__device__ float g_cvec2 [HDIM];
__device__ float g_zero  [HDIM];          // stays zero (bias for fold GEMMs)
__device__ float g_x     [(size_t)NT * HDIM];
__device__ float g_x2    [(size_t)NT * HDIM];
__device__ float g_xp    [(size_t)NT * 1024];
__device__ float g_d1    [(size_t)NT * DTR];
__device__ float g_Bm    [(size_t)NT * SDIM];
__device__ float g_Cm    [(size_t)NT * SDIM];
__device__ float g_dwT   [DTR * EDIM];
__device__ float g_bwT   [DTR * EDIM];
__device__ float g_cwT   [DTR * EDIM];
// adjacency neighbor lists (built once, used by both aggregations)
__device__ int   g_ncnt  [NT];
__device__ int   g_nidx  [(size_t)NT * NNODE];
// 16-bit operand buffers
__device__ ush g_c1h[(size_t)NT * 512];
__device__ ush g_c1l[(size_t)NT * 512];
__device__ ush g_xh [(size_t)NT * HDIM];
__device__ ush g_xl [(size_t)NT * HDIM];
__device__ ush g_qh [(size_t)NT * HDIM];
__device__ ush g_kh [(size_t)NT * HDIM];
__device__ ush g_wh [1024 * 512];
__device__ ush g_wl [1024 * 512];

__device__ __forceinline__ void bsplit16(float v, ush& h, ush& l) {  // bf16
    __nv_bfloat16 hh = __float2bfloat16(v);
    __nv_bfloat16 ll = __float2bfloat16(v - __bfloat162float(hh));
    h = *reinterpret_cast<ush*>(&hh);
    l = *reinterpret_cast<ush*>(&ll);
}
__device__ __forceinline__ void fsplit16(float v, ush& h, ush& l) {  // fp16
    __half hh = __float2half(v);
    __half ll = __float2half(v - __half2float(hh));
    h = *reinterpret_cast<ush*>(&hh);
    l = *reinterpret_cast<ush*>(&ll);
}
__device__ __forceinline__ ush f2h16(float v) {
    __half hh = __float2half(v);
    return *reinterpret_cast<ush*>(&hh);
}

// ===========================================================================
// Fast math (FMA-pipe exp)
// ===========================================================================
__device__ __forceinline__ float fast_exp(float x) {
    x = fminf(fmaxf(x, -87.0f), 87.0f);
    float y = x * 1.44269504088896340736f;
    float t = y + 12582912.0f;
    int   e = __float_as_int(t) - 0x4B400000;
    float r = t - 12582912.0f;
    float f = (y - r) * 0.69314718055994530942f;
    float p = 1.3888889e-3f;
    p = fmaf(p, f, 8.3333333e-3f);
    p = fmaf(p, f, 4.1666668e-2f);
    p = fmaf(p, f, 1.6666667e-1f);
    p = fmaf(p, f, 0.5f);
    p = fmaf(p, f, 1.0f);
    p = fmaf(p, f, 1.0f);
    float s = __int_as_float((e + 127) << 23);
    return p * s;
}
__device__ __forceinline__ float fast_sigmoid(float x) {
    return 1.0f / (1.0f + fast_exp(-x));
}
__device__ __forceinline__ float fast_softplus(float x) {
    if (x > 20.0f) return x;
    return log1pf(fast_exp(x));
}

// ===========================================================================
// Warp MMA / async-copy primitives (baseline sm_80+ only)
// ===========================================================================
__device__ __forceinline__ uint32_t smem_u32(const void* p) {
    uint32_t a;
    asm("{ .reg .u64 t; cvta.to.shared.u64 t, %1; cvt.u32.u64 %0, t; }"
        : "=r"(a) : "l"(p));
    return a;
}
__device__ __forceinline__ void ldsm_x4(uint32_t* r, uint32_t addr) {
    asm volatile("ldmatrix.sync.aligned.m8n8.x4.shared.b16 {%0,%1,%2,%3}, [%4];"
        : "=r"(r[0]), "=r"(r[1]), "=r"(r[2]), "=r"(r[3]) : "r"(addr));
}
__device__ __forceinline__ void mma_bf16(float* c, const uint32_t* a,
                                         uint32_t b0, uint32_t b1) {
    asm volatile(
        "mma.sync.aligned.m16n8k16.row.col.f32.bf16.bf16.f32 "
        "{%0,%1,%2,%3}, {%4,%5,%6,%7}, {%8,%9}, {%0,%1,%2,%3};"
        : "+f"(c[0]), "+f"(c[1]), "+f"(c[2]), "+f"(c[3])
        : "r"(a[0]), "r"(a[1]), "r"(a[2]), "r"(a[3]), "r"(b0), "r"(b1));
}
__device__ __forceinline__ void mma_f16(float* c, const uint32_t* a,
                                        uint32_t b0, uint32_t b1) {
    asm volatile(
        "mma.sync.aligned.m16n8k16.row.col.f32.f16.f16.f32 "
        "{%0,%1,%2,%3}, {%4,%5,%6,%7}, {%8,%9}, {%0,%1,%2,%3};"
        : "+f"(c[0]), "+f"(c[1]), "+f"(c[2]), "+f"(c[3])
        : "r"(a[0]), "r"(a[1]), "r"(a[2]), "r"(a[3]), "r"(b0), "r"(b1));
}
__device__ __forceinline__ void cp_async16(uint32_t saddr, const void* gaddr) {
    asm volatile("cp.async.cg.shared.global [%0], [%1], 16;"
        :: "r"(saddr), "l"(gaddr));
}
#define CP_COMMIT()  asm volatile("cp.async.commit_group;" ::: "memory")
#define CP_WAIT(n)   asm volatile("cp.async.wait_group %0;" :: "n"(n) : "memory")

// ===========================================================================
// HMMA split GEMM: C[M,Nc] = A[M,K] @ B[Nc,K]^T (fp32 acc)
// FTAIL=0 (bf16, nseg=3 near-exact) / FTAIL=1 (fp16; nseg=2 or 1)
// seg 0: Ah*Bh   seg 1: Al*Bh   seg 2: Ah*Bl
// mode 0: fp32 out (+bias)
// mode 1: score head (probs+logits)
// mode 2: fp16 output (hi only)
// mode 3: out_proj fused epilogue (residual + transpose + fp16 copy)
// mode 4: fp32 out + bias + cnt[row]*cvec[col]   (addrow = cvec)
// ===========================================================================
template<int FTAIL>
__global__ void __launch_bounds__(128, 2) gemm_k(
    const ush* __restrict__ Ah, const ush* __restrict__ Al,
    const ush* __restrict__ Bh, const ush* __restrict__ Bl,
    const float* __restrict__ bias, const float* __restrict__ addrow,
    const int* __restrict__ cntp,
    void* __restrict__ out1, void* __restrict__ out2,
    const float* __restrict__ gb_ptr,
    int K, int Nc, int mode, int nseg,
    size_t aBatch, size_t bBatch, size_t cBatch)
{
    extern __shared__ __align__(16) char smem[];
    const uint32_t sb = smem_u32(smem);
    const int tid = threadIdx.x;
    const int wid = tid >> 5, lane = tid & 31;
    const int wm = wid & 1, wn = wid >> 1;

    const size_t zA = (size_t)blockIdx.z * aBatch;
    const size_t zB = (size_t)blockIdx.z * bBatch;
    const ush* Aseg[3] = { Ah + zA, Al + zA, Ah + zA };
    const ush* Bseg[3] = { Bh + zB, Bh + zB, Bl + zB };

    const int m0 = blockIdx.y * 128, n0 = blockIdx.x * 128;
    const int ksub = K >> 6;
    const int nk = nseg * ksub;

    float acc[4][8][4];
#pragma unroll
    for (int i = 0; i < 4; i++)
#pragma unroll
        for (int j = 0; j < 8; j++)
#pragma unroll
            for (int r = 0; r < 4; r++) acc[i][j][r] = 0.0f;

    const int a_r = ((lane >> 3) & 1) * 8 + (lane & 7);
    const int a_c = ((lane >> 4) & 1) * 8;
    const int b_n = ((lane >> 4) & 1) * 8 + (lane & 7);
    const int b_k = ((lane >> 3) & 1) * 8;

    auto load_tile = [&](const ush* g, int row0, int k0, uint32_t sdst) {
#pragma unroll
        for (int j = 0; j < 8; j++) {
            int c = tid + j * 128;          // 0..1023
            int row = c >> 3, ch = c & 7;
            const void* gp = g + (size_t)(row0 + row) * K + k0 + ch * 8;
            uint32_t sp = sdst + SMEM_SWIZZLE_128B((uint32_t)(row * 128 + ch * 16));
            cp_async16(sp, gp);
        }
    };

    load_tile(Aseg[0], m0, 0, sb);
    load_tile(Bseg[0], n0, 0, sb + 16384);
    CP_COMMIT();

    for (int i = 0; i < nk; i++) {
        int b = i & 1;
        if (i + 1 < nk) {
            int seg = (i + 1) / ksub;
            int k0 = ((i + 1) - seg * ksub) << 6;
            uint32_t sd = sb + (uint32_t)(b ^ 1) * 32768u;
            load_tile(Aseg[seg], m0, k0, sd);
            load_tile(Bseg[seg], n0, k0, sd + 16384);
            CP_COMMIT();
            CP_WAIT(1);
        } else {
            CP_COMMIT();
            CP_WAIT(0);
        }
        __syncthreads();

        uint32_t abase = sb + (uint32_t)b * 32768u;
        uint32_t bbase = abase + 16384u;
#pragma unroll
        for (int ks = 0; ks < 4; ks++) {
            uint32_t afr[4][4];
#pragma unroll
            for (int mi = 0; mi < 4; mi++) {
                int row = wm * 64 + mi * 16 + a_r;
                int col = ks * 16 + a_c;
                ldsm_x4(afr[mi],
                        abase + SMEM_SWIZZLE_128B((uint32_t)(row * 128 + col * 2)));
            }
            uint32_t bfr[4][4];
#pragma unroll
            for (int j = 0; j < 4; j++) {
                int n = wn * 64 + j * 16 + b_n;
                int kc = ks * 16 + b_k;
                ldsm_x4(bfr[j],
                        bbase + SMEM_SWIZZLE_128B((uint32_t)(n * 128 + kc * 2)));
            }
#pragma unroll
            for (int mi = 0; mi < 4; mi++)
#pragma unroll
                for (int ni = 0; ni < 8; ni++) {
                    const uint32_t* bs = bfr[ni >> 1];
                    if (FTAIL)
                        mma_f16(acc[mi][ni], afr[mi],
                                bs[(ni & 1) * 2], bs[(ni & 1) * 2 + 1]);
                    else
                        mma_bf16(acc[mi][ni], afr[mi],
                                 bs[(ni & 1) * 2], bs[(ni & 1) * 2 + 1]);
                }
        }
        __syncthreads();
    }

    // ---------------- epilogue ----------------
    const int rg = lane >> 2;
    const int cg = (lane & 3) * 2;
#pragma unroll
    for (int mi = 0; mi < 4; mi++) {
#pragma unroll
        for (int ni = 0; ni < 8; ni++) {
            float* c = acc[mi][ni];
            int gr0 = m0 + wm * 64 + mi * 16 + rg;
            int gc  = n0 + wn * 64 + ni * 8 + cg;
            if (mode == 0) {
                float* C = (float*)out1;
                float b0 = bias ? bias[gc] : 0.0f;
                float b1 = bias ? bias[gc + 1] : 0.0f;
                *(float2*)(C + (size_t)gr0 * Nc + gc)       = {c[0] + b0, c[1] + b1};
                *(float2*)(C + (size_t)(gr0 + 8) * Nc + gc) = {c[2] + b0, c[3] + b1};
            } else if (mode == 1) {
                float gb = *gb_ptr;
                float* P = (float*)out1 + (size_t)blockIdx.z * cBatch;
                float* L = (float*)out2 + (size_t)blockIdx.z * cBatch;
                float l0 = c[0] * 0.0625f + gb, l1 = c[1] * 0.0625f + gb;
                float l2 = c[2] * 0.0625f + gb, l3 = c[3] * 0.0625f + gb;
                *(float2*)(L + (size_t)gr0 * Nc + gc)       = {l0, l1};
                *(float2*)(L + (size_t)(gr0 + 8) * Nc + gc) = {l2, l3};
                *(float2*)(P + (size_t)gr0 * Nc + gc)       =
                    {fast_sigmoid(l0), fast_sigmoid(l1)};
                *(float2*)(P + (size_t)(gr0 + 8) * Nc + gc) =
                    {fast_sigmoid(l2), fast_sigmoid(l3)};
            } else if (mode == 2) {  // fp16 output (hi only)
                ush* H = (ush*)out1;
                H[(size_t)gr0 * Nc + gc]           = f2h16(c[0]);
                H[(size_t)gr0 * Nc + gc + 1]       = f2h16(c[1]);
                H[(size_t)(gr0 + 8) * Nc + gc]     = f2h16(c[2]);
                H[(size_t)(gr0 + 8) * Nc + gc + 1] = f2h16(c[3]);
            } else if (mode == 3) {  // out_proj fused residual+transpose+fp16
                float* O = (float*)out1;
                ush*   H = (ush*)out2;
                int t0 = gr0 & 31, nn0 = gr0 >> 5;
                size_t d0 = ((size_t)t0 * NNODE + nn0) * Nc + gc;
                float v0 = c[0] + bias[gc]     + addrow[d0];
                float v1 = c[1] + bias[gc + 1] + addrow[d0 + 1];
                *(float2*)(O + d0) = {v0, v1};
                H[d0] = f2h16(v0); H[d0 + 1] = f2h16(v1);
                int t1 = (gr0 + 8) & 31, nn1 = (gr0 + 8) >> 5;
                size_t d1 = ((size_t)t1 * NNODE + nn1) * Nc + gc;
                float v2 = c[2] + bias[gc]     + addrow[d1];
                float v3 = c[3] + bias[gc + 1] + addrow[d1 + 1];
                *(float2*)(O + d1) = {v2, v3};
                H[d1] = f2h16(v2); H[d1 + 1] = f2h16(v3);
            } else {  // mode 4: + bias + cnt[row]*cvec[col]
                float* C = (float*)out1;
                float cn0 = (float)cntp[gr0];
                float cn1 = (float)cntp[gr0 + 8];
                float b0 = bias[gc]     + cn0 * addrow[gc];
                float b1 = bias[gc + 1] + cn0 * addrow[gc + 1];
                float b2 = bias[gc]     + cn1 * addrow[gc];
                float b3 = bias[gc + 1] + cn1 * addrow[gc + 1];
                *(float2*)(C + (size_t)gr0 * Nc + gc)       = {c[0] + b0, c[1] + b1};
                *(float2*)(C + (size_t)(gr0 + 8) * Nc + gc) = {c[2] + b2, c[3] + b3};
            }
        }
    }
}

// ===========================================================================
// Small SIMT SGEMM (exact fp32): C = A[M,K]@B[K,N] + bias
// ===========================================================================
__global__ void __launch_bounds__(256) sgemm_nn(
    const float* __restrict__ A, const float* __restrict__ B,
    const float* __restrict__ bias, float* __restrict__ C,
    int M, int Nc, int K)
{
    __shared__ float As[8][128];
    __shared__ float Bs[8][128];
    int tid = threadIdx.x;
    int bx = blockIdx.x, by = blockIdx.y;
    int tx = tid & 15, ty = tid >> 4;
    int arow = tid >> 1, acol = (tid & 1) * 4;
    int brow = tid >> 5, bcol = (tid & 31) * 4;
    const float* Ab = A + (size_t)by * 128 * K;
    const float* Bb = B + (size_t)bx * 128;
    float acc[8][8] = {};
    for (int k0 = 0; k0 < K; k0 += 8) {
        float4 av = *(const float4*)(Ab + (size_t)arow * K + k0 + acol);
        As[acol + 0][arow] = av.x; As[acol + 1][arow] = av.y;
        As[acol + 2][arow] = av.z; As[acol + 3][arow] = av.w;
        *(float4*)&Bs[brow][bcol] =
            *(const float4*)(Bb + (size_t)(k0 + brow) * Nc + bcol);
        __syncthreads();
#pragma unroll
        for (int kk = 0; kk < 8; kk++) {
            float4 a0 = *(float4*)&As[kk][ty * 8];
            float4 a1 = *(float4*)&As[kk][ty * 8 + 4];
            float4 b0 = *(float4*)&Bs[kk][tx * 8];
            float4 b1 = *(float4*)&Bs[kk][tx * 8 + 4];
            float ar[8] = {a0.x, a0.y, a0.z, a0.w, a1.x, a1.y, a1.z, a1.w};
            float br[8] = {b0.x, b0.y, b0.z, b0.w, b1.x, b1.y, b1.z, b1.w};
#pragma unroll
            for (int i = 0; i < 8; i++)
#pragma unroll
                for (int j = 0; j < 8; j++)
                    acc[i][j] = fmaf(ar[i], br[j], acc[i][j]);
        }
        __syncthreads();
    }
#pragma unroll
    for (int i = 0; i < 8; i++) {
        int r = by * 128 + ty * 8 + i;
#pragma unroll
        for (int j = 0; j < 8; j += 4) {
            int c = bx * 128 + tx * 8 + j;
            float4 v;
            v.x = acc[i][j] + bias[c];         v.y = acc[i][j + 1] + bias[c + 1];
            v.z = acc[i][j + 2] + bias[c + 2]; v.w = acc[i][j + 3] + bias[c + 3];
            *(float4*)(C + (size_t)r * Nc + c) = v;
        }
    }
}

// ===========================================================================
// Elementwise / helper kernels
// ===========================================================================
__global__ void pe_kernel() {
    int n = blockIdx.x;
    int i = threadIdx.x;  // 0..127
    float div = expf((float)(2 * i) * (-0.03597867333f));
    float ang = (float)n * div;
    g_pe[n * PDIM + 2 * i]     = sinf(ang);
    g_pe[n * PDIM + 2 * i + 1] = cosf(ang);
}

// cvec[h] = sum_k b[k] * Wbot[k*256+h]   (blockIdx 0 -> cvec1, 1 -> cvec2)
__global__ void cvec_kernel(const float* __restrict__ b1,
                            const float* __restrict__ W1bot,
                            const float* __restrict__ b2,
                            const float* __restrict__ W2bot)
{
    int h = threadIdx.x;
    const float* b = blockIdx.x ? b2 : b1;
    const float* W = blockIdx.x ? W2bot : W1bot;
    float acc = 0.0f;
    for (int k = 0; k < 256; k++)
        acc = fmaf(b[k], W[k * 256 + h], acc);
    (blockIdx.x ? g_cvec2 : g_cvec1)[h] = acc;
}

// weight transpose+split into concat-K layout: W[K,N] -> g_wh/g_wl [N, ktot]
// at k-offset koff.  dt: 0 = bf16 hi+lo, 1 = fp16 hi only
__global__ void split_wT(const float* __restrict__ W, int K, int N,
                         int ktot, int koff, int dt) {
    int i = blockIdx.x * 256 + threadIdx.x;
    if (i < K * N) {
        int k = i / N, n = i % N;
        size_t d = (size_t)n * ktot + koff + k;
        if (dt == 0) {
            ush h, l; bsplit16(W[i], h, l);
            g_wh[d] = h;
            g_wl[d] = l;
        } else {
            g_wh[d] = f2h16(W[i]);
        }
    }
}

// Build adjacency neighbor lists once
__global__ void build_nbr(const float* __restrict__ adj) {
    int i = blockIdx.x, t = blockIdx.y;
    size_t row = (size_t)t * NNODE + i;
    const float4* a4 = (const float4*)(adj + row * NNODE);
    __shared__ int s_idx[NNODE];
    __shared__ int s_cnt;
    if (threadIdx.x == 0) s_cnt = 0;
    __syncthreads();
    float4 v = a4[threadIdx.x];
    int j0 = threadIdx.x * 4;
    if (v.x != 0.0f) s_idx[atomicAdd(&s_cnt, 1)] = j0;
    if (v.y != 0.0f) s_idx[atomicAdd(&s_cnt, 1)] = j0 + 1;
    if (v.z != 0.0f) s_idx[atomicAdd(&s_cnt, 1)] = j0 + 2;
    if (v.w != 0.0f) s_idx[atomicAdd(&s_cnt, 1)] = j0 + 3;
    __syncthreads();
    int cnt = s_cnt;
    if (threadIdx.x == 0) g_ncnt[row] = cnt;
    for (int p = threadIdx.x; p < cnt; p += 256)
        g_nidx[row * NNODE + p] = s_idx[p];
}

// Layer-1 FUSED: gather(pre1) + pebase + cnt*cvec1 + relu + LN ->
// g_x fp32 and bf16 split into c1h/c1l cols [0,256)
__global__ void gather1_fused(const float* __restrict__ gam,
                              const float* __restrict__ bet)
{
    int i = blockIdx.x, t = blockIdx.y;
    size_t row = (size_t)t * NNODE + i;
    int cnt = g_ncnt[row];
    const int* idx = g_nidx + row * NNODE;
    int h = threadIdx.x;
    float acc = g_pebase[(size_t)i * HDIM + h] + (float)cnt * g_cvec1[h];
    for (int p = 0; p < cnt; p++)
        acc += g_pre1[(size_t)idx[p] * HDIM + h];
    float v = fmaxf(acc, 0.0f);
    float s = v, q = v * v;
#pragma unroll
    for (int o = 16; o > 0; o >>= 1) {
        s += __shfl_xor_sync(0xffffffffu, s, o);
        q += __shfl_xor_sync(0xffffffffu, q, o);
    }
    __shared__ float ss[8], qq[8];
    __shared__ float s_mu, s_rstd;
    int w = h >> 5;
    if ((h & 31) == 0) { ss[w] = s; qq[w] = q; }
    __syncthreads();
    if (h == 0) {
        float S = 0, QQ = 0;
        for (int j = 0; j < 8; j++) { S += ss[j]; QQ += qq[j]; }
        float mu = S * (1.0f / 256.0f);
        float var = QQ * (1.0f / 256.0f) - mu * mu;
        s_mu = mu; s_rstd = rsqrtf(var + 1e-5f);
    }
    __syncthreads();
    float o = (v - s_mu) * s_rstd * gam[h] + bet[h];
    g_x[row * HDIM + h] = o;
    ush hh, ll; bsplit16(o, hh, ll);
    g_c1h[row * 512 + h] = hh;
    g_c1l[row * 512 + h] = ll;
}

// Layer-2 gather of x (per-t), bf16 split into c1h/c1l cols [256,512)
__global__ void gather2(void) {
    int i = blockIdx.x, t = blockIdx.y;
    size_t row = (size_t)t * NNODE + i;
    int cnt = g_ncnt[row];
    const int* idx = g_nidx + row * NNODE;
    int h = threadIdx.x;
    const float* mb = g_x + (size_t)t * NNODE * HDIM;
    float acc = 0.0f;
    for (int p = 0; p < cnt; p++)
        acc += mb[(size_t)idx[p] * HDIM + h];
    ush hi, lo; bsplit16(acc, hi, lo);
    g_c1h[row * 512 + 256 + h] = hi;
    g_c1l[row * 512 + 256 + h] = lo;
}

// ReLU + LN (fp32 in/out only; used for x2)
__global__ void relu_ln_kernel(const float* __restrict__ in,
                               const float* __restrict__ gam,
                               const float* __restrict__ bet,
                               float* __restrict__ out)
{
    int row = blockIdx.x, tid = threadIdx.x;
    float v = fmaxf(in[(size_t)row * HDIM + tid], 0.0f);
    float s = v, q = v * v;
#pragma unroll
    for (int o = 16; o > 0; o >>= 1) {
        s += __shfl_xor_sync(0xffffffffu, s, o);
        q += __shfl_xor_sync(0xffffffffu, q, o);
    }
    __shared__ float ss[8], qq[8];
    __shared__ float s_mu, s_rstd;
    int w = tid >> 5;
    if ((tid & 31) == 0) { ss[w] = s; qq[w] = q; }
    __syncthreads();
    if (tid == 0) {
        float S = 0, QQ = 0;
        for (int i = 0; i < 8; i++) { S += ss[i]; QQ += qq[i]; }
        float mu = S * (1.0f / 256.0f);
        float var = QQ * (1.0f / 256.0f) - mu * mu;
        s_mu = mu; s_rstd = rsqrtf(var + 1e-5f);
    }
    __syncthreads();
    out[(size_t)row * HDIM + tid] = (v - s_mu) * s_rstd * gam[tid] + bet[tid];
}

// Mamba pre-LN: read x2 (t-major), write bf16 splits xn (n-major)
__global__ void ln_seq_split(const float* __restrict__ gam,
                             const float* __restrict__ bet)
{
    int rin = blockIdx.x;              // t*N + n
    int tid = threadIdx.x;
    int t = rin >> 10, n = rin & 1023;
    float v = g_x2[(size_t)rin * HDIM + tid];
    float s = v, q = v * v;
#pragma unroll
    for (int o = 16; o > 0; o >>= 1) {
        s += __shfl_xor_sync(0xffffffffu, s, o);
        q += __shfl_xor_sync(0xffffffffu, q, o);
    }
    __shared__ float ss[8], qq[8];
    __shared__ float s_mu, s_rstd;
    int w = tid >> 5;
    if ((tid & 31) == 0) { ss[w] = s; qq[w] = q; }
    __syncthreads();
    if (tid == 0) {
        float S = 0, QQ = 0;
        for (int i = 0; i < 8; i++) { S += ss[i]; QQ += qq[i]; }
        float mu = S * (1.0f / 256.0f);
        float var = QQ * (1.0f / 256.0f) - mu * mu;
        s_mu = mu; s_rstd = rsqrtf(var + 1e-5f);
    }
    __syncthreads();
    float o = (v - s_mu) * s_rstd * gam[tid] + bet[tid];
    size_t dst = ((size_t)n * TSTEP + t) * HDIM + tid;
    ush h, l; bsplit16(o, h, l);
    g_xh[dst] = h; g_xl[dst] = l;
}

__global__ void transpose_w3(const float* __restrict__ dw,
                             const float* __restrict__ bw,
                             const float* __restrict__ cw)
{
    int id = blockIdx.x * 256 + threadIdx.x;  // 8192
    if (id < EDIM * DTR) {
        int k = id >> 4, n = id & 15;
        g_dwT[n * EDIM + k] = dw[id];
        g_bwT[n * EDIM + k] = bw[id];
        g_cwT[n * EDIM + k] = cw[id];
    }
}

// proj3 with inline silu on xp
__global__ void proj3_kernel(const float* __restrict__ db,
                             const float* __restrict__ bb,
                             const float* __restrict__ cb)
{
    int r = blockIdx.x * 16 + (threadIdx.x >> 4);
    int n = threadIdx.x & 15;
    const float4* a4 = (const float4*)(g_xp + (size_t)r * 1024);
    const float4* d4 = (const float4*)(g_dwT + n * EDIM);
    const float4* b4 = (const float4*)(g_bwT + n * EDIM);
    const float4* c4 = (const float4*)(g_cwT + n * EDIM);
    float ad = 0, ab = 0, ac = 0;
#pragma unroll 4
    for (int k = 0; k < EDIM / 4; k++) {
        float4 a = a4[k];
        a.x *= fast_sigmoid(a.x); a.y *= fast_sigmoid(a.y);
        a.z *= fast_sigmoid(a.z); a.w *= fast_sigmoid(a.w);
        float4 d = d4[k], b = b4[k], c = c4[k];
        ad = fmaf(a.x, d.x, fmaf(a.y, d.y, fmaf(a.z, d.z, fmaf(a.w, d.w, ad))));
        ab = fmaf(a.x, b.x, fmaf(a.y, b.y, fmaf(a.z, b.z, fmaf(a.w, b.w, ab))));
        ac = fmaf(a.x, c.x, fmaf(a.y, c.y, fmaf(a.z, c.z, fmaf(a.w, c.w, ac))));
    }
    size_t o = (size_t)r * 16 + n;
    g_d1[o] = ad + db[n];
    g_Bm[o] = ab + bb[n];
    g_Cm[o] = ac + cb[n];
}

// Selective scan with FUSED delta computation (softplus(d1@dt_w + dt_b))
// and inline silu on xp; writes y as fp16 splits into g_c1h/g_c1l
__global__ void __launch_bounds__(512) scan_kernel(
    const float* __restrict__ A_log, const float* __restrict__ D_vec,
    const float* __restrict__ dtw, const float* __restrict__ dtb)
{
    int n = blockIdx.x;
    int e = threadIdx.x;
    float A[SDIM], h[SDIM], wreg[DTR];
#pragma unroll
    for (int s = 0; s < SDIM; s++) {
        A[s] = -fast_exp(A_log[e * SDIM + s]);
        h[s] = 0.0f;
    }
#pragma unroll
    for (int k = 0; k < DTR; k++)
        wreg[k] = dtw[k * EDIM + e];
    float dbv = dtb[e];
    float Dv = D_vec[e];
    __shared__ float sbv[TSTEP * SDIM], scv[TSTEP * SDIM], sd1[TSTEP * DTR];
    sbv[e] = g_Bm[(size_t)n * (TSTEP * SDIM) + e];
    scv[e] = g_Cm[(size_t)n * (TSTEP * SDIM) + e];
    sd1[e] = g_d1[(size_t)n * (TSTEP * DTR) + e];
    __syncthreads();
    for (int t = 0; t < TSTEP; t++) {
        size_t r = (size_t)n * TSTEP + t;
        const float* sb = sbv + t * SDIM;
        const float* sc = scv + t * SDIM;
        const float* d1 = sd1 + t * DTR;
        float dacc = dbv;
#pragma unroll
        for (int k = 0; k < DTR; k++)
            dacc = fmaf(d1[k], wreg[k], dacc);
        float dt = fast_softplus(dacc);
        float xv = g_xp[r * 1024 + e];
        float xt = xv * fast_sigmoid(xv);
        float dx = dt * xt;
        float yv = 0.0f;
#pragma unroll
        for (int s = 0; s < SDIM; s++) {
            h[s] = fmaf(fast_exp(dt * A[s]), h[s], dx * sb[s]);
            yv   = fmaf(sc[s], h[s], yv);
        }
        yv += xt * Dv;
        float g = g_xp[r * 1024 + EDIM + e];
        yv *= g * fast_sigmoid(g);
        ush hi, lo; fsplit16(yv, hi, lo);
        g_c1h[r * EDIM + e] = hi;
        g_c1l[r * EDIM + e] = lo;
    }
}

// ===========================================================================
// Host launch
// ===========================================================================
#define GEMM_SMEM 65536

extern "C" void kernel_launch(void* const* d_in, const int* in_sizes, int n_in,
                              void* d_out, int out_size)
{
    const float* adj     = (const float*)d_in[0];
    const float* msg1_w  = (const float*)d_in[1];
    const float* msg1_b  = (const float*)d_in[2];
    const float* upd1_w  = (const float*)d_in[3];
    const float* upd1_b  = (const float*)d_in[4];
    const float* ln1_g   = (const float*)d_in[5];
    const float* ln1_b   = (const float*)d_in[6];
    const float* msg2_w  = (const float*)d_in[7];
    const float* msg2_b  = (const float*)d_in[8];
    const float* upd2_w  = (const float*)d_in[9];
    const float* upd2_b  = (const float*)d_in[10];
    const float* ln2_g   = (const float*)d_in[11];
    const float* ln2_b   = (const float*)d_in[12];
    const float* mbln_g  = (const float*)d_in[13];
    const float* mbln_b  = (const float*)d_in[14];
    const float* in_w    = (const float*)d_in[15];
    const float* in_b    = (const float*)d_in[16];
    const float* delta_w = (const float*)d_in[17];
    const float* delta_b = (const float*)d_in[18];
    const float* dt_w    = (const float*)d_in[19];
    const float* dt_b    = (const float*)d_in[20];
    const float* Bp_w    = (const float*)d_in[21];
    const float* Bp_b    = (const float*)d_in[22];
    const float* Cp_w    = (const float*)d_in[23];
    const float* Cp_b    = (const float*)d_in[24];
    const float* A_log   = (const float*)d_in[25];
    const float* D_vec   = (const float*)d_in[26];
    const float* out_w   = (const float*)d_in[27];
    const float* out_b   = (const float*)d_in[28];
    const float* q_w     = (const float*)d_in[29];
    const float* k_w     = (const float*)d_in[30];
    const float* gate_b  = (const float*)d_in[31];

    float* out    = (float*)d_out;
    float* outs   = out;                                    // [T,N,H]
    float* probs  = out + (size_t)TSTEP * NNODE * HDIM;     // [T,N,N]
    float* logits = probs + (size_t)TSTEP * NNODE * NNODE;  // [T,N,N]

    cudaFuncSetAttribute(gemm_k<0>, cudaFuncAttributeMaxDynamicSharedMemorySize,
                         GEMM_SMEM);
    cudaFuncSetAttribute(gemm_k<1>, cudaFuncAttributeMaxDynamicSharedMemorySize,
                         GEMM_SMEM);

    float *pe_, *pre1_, *pebase_, *M1c_, *M2c_, *cvec2_, *zero_;
    float *x_, *x2_, *xp_;
    int* cnt_;
    ush *c1h_, *c1l_, *xh_, *xl_, *qh_, *kh_, *wh_, *wl_;
    cudaGetSymbolAddress((void**)&pe_,     g_pe);
    cudaGetSymbolAddress((void**)&pre1_,   g_pre1);
    cudaGetSymbolAddress((void**)&pebase_, g_pebase);
    cudaGetSymbolAddress((void**)&M1c_,    g_M1c);
    cudaGetSymbolAddress((void**)&M2c_,    g_M2c);
    cudaGetSymbolAddress((void**)&cvec2_,  g_cvec2);
    cudaGetSymbolAddress((void**)&zero_,   g_zero);
    cudaGetSymbolAddress((void**)&x_,      g_x);
    cudaGetSymbolAddress((void**)&x2_,     g_x2);
    cudaGetSymbolAddress((void**)&xp_,     g_xp);
    cudaGetSymbolAddress((void**)&cnt_,    g_ncnt);
    cudaGetSymbolAddress((void**)&c1h_,    g_c1h);
    cudaGetSymbolAddress((void**)&c1l_,    g_c1l);
    cudaGetSymbolAddress((void**)&xh_,     g_xh);
    cudaGetSymbolAddress((void**)&xl_,     g_xl);
    cudaGetSymbolAddress((void**)&qh_,     g_qh);
    cudaGetSymbolAddress((void**)&kh_,     g_kh);
    cudaGetSymbolAddress((void**)&wh_,     g_wh);
    cudaGetSymbolAddress((void**)&wl_,     g_wl);

    const float* W1bot = upd1_w + 256 * 256;
    const float* W2bot = upd2_w + 256 * 256;

    // 1. PE + neighbor lists + weight folds (all exact fp32)
    pe_kernel<<<NNODE, 128>>>();
    build_nbr<<<dim3(NNODE, TSTEP), 256>>>(adj);
    sgemm_nn<<<dim3(2, 2), 256>>>(msg1_w, W1bot, zero_, M1c_, 256, 256, 256);
    sgemm_nn<<<dim3(2, 2), 256>>>(msg2_w, W2bot, zero_, M2c_, 256, 256, 256);
    cvec_kernel<<<2, 256>>>(msg1_b, W1bot, msg2_b, W2bot);
    sgemm_nn<<<dim3(2, 8), 256>>>(pe_, M1c_, zero_, pre1_, NNODE, 256, 256);
    sgemm_nn<<<dim3(2, 8), 256>>>(pe_, upd1_w, upd1_b, pebase_, NNODE, 256, 256);
    // 2. layer 1: fused gather+relu+LN (no NT GEMM at all)
    gather1_fused<<<dim3(NNODE, TSTEP), 256>>>(ln1_g, ln1_b);
    // 3. layer 2: gather x; combined [x|aggx] @ [W2top; M2c] GEMM (mode 4)
    gather2<<<dim3(NNODE, TSTEP), 256>>>();
    split_wT<<<(256 * 256 + 255) / 256, 256>>>(upd2_w, 256, 256, 512, 0, 0);
    split_wT<<<(256 * 256 + 255) / 256, 256>>>(M2c_, 256, 256, 512, 256, 0);
    gemm_k<0><<<dim3(2, NT / 128), 128, GEMM_SMEM>>>(
        c1h_, c1l_, wh_, wl_, upd2_b, cvec2_, cnt_, x2_, nullptr, nullptr,
        512, 256, 4, 3, 0, 0, 0);
    relu_ln_kernel<<<NT, 256>>>(x2_, ln2_g, ln2_b, x2_);
    // 4. Mamba: LN+transpose -> xh/xl; in_proj GEMM
    ln_seq_split<<<NT, 256>>>(mbln_g, mbln_b);
    split_wT<<<(256 * 1024 + 255) / 256, 256>>>(in_w, 256, 1024, 256, 0, 0);
    gemm_k<0><<<dim3(8, NT / 128), 128, GEMM_SMEM>>>(
        xh_, xl_, wh_, wl_, in_b, nullptr, nullptr, xp_, nullptr, nullptr,
        256, 1024, 0, 3, 0, 0, 0);
    // 5. small projections (inline silu)
    transpose_w3<<<(EDIM * DTR + 255) / 256, 256>>>(delta_w, Bp_w, Cp_w);
    proj3_kernel<<<NT / 16, 256>>>(delta_b, Bp_b, Cp_b);
    // 6. scan (fused delta + silu; writes y fp16 splits into c1h/c1l)
    scan_kernel<<<NNODE, EDIM>>>(A_log, D_vec, dt_w, dt_b);
    // 7. out projection (fp16 2-pass) with fused residual+transpose epilogue
    split_wT<<<(512 * 256 + 255) / 256, 256>>>(out_w, 512, 256, 512, 0, 1);
    gemm_k<1><<<dim3(2, NT / 128), 128, GEMM_SMEM>>>(
        c1h_, c1l_, wh_, nullptr, out_b, x2_, nullptr, outs, xh_, nullptr,
        512, 256, 3, 2, 0, 0, 0);
    // 8. q/k GEMMs (fp16 1-pass), then score head (fp16 1-pass)
    split_wT<<<(256 * 256 + 255) / 256, 256>>>(q_w, 256, 256, 256, 0, 1);
    gemm_k<1><<<dim3(2, NT / 128), 128, GEMM_SMEM>>>(
        xh_, nullptr, wh_, nullptr, nullptr, nullptr, nullptr, qh_, nullptr,
        nullptr, 256, 256, 2, 1, 0, 0, 0);
    split_wT<<<(256 * 256 + 255) / 256, 256>>>(k_w, 256, 256, 256, 0, 1);
    gemm_k<1><<<dim3(2, NT / 128), 128, GEMM_SMEM>>>(
        xh_, nullptr, wh_, nullptr, nullptr, nullptr, nullptr, kh_, nullptr,
        nullptr, 256, 256, 2, 1, 0, 0, 0);
    gemm_k<1><<<dim3(8, 8, TSTEP), 128, GEMM_SMEM>>>(
        qh_, nullptr, kh_, nullptr, nullptr, nullptr, nullptr, probs, logits,
        gate_b, 256, 1024, 1, 1,
        (size_t)NNODE * HDIM, (size_t)NNODE * HDIM, (size_t)NNODE * NNODE);
}

// round 15
// speedup vs baseline: 1.0522x; 1.0522x over previous
#include <cuda_runtime.h>
#include <cuda_fp16.h>
#include <cuda_bf16.h>
#include <cstdint>

// Problem constants
#define NNODE 1024
#define TSTEP 32
#define HDIM  256
#define PDIM  256
#define EDIM  512
#define DTR   16
#define SDIM  16
#define NT    (NNODE * TSTEP)   // 32768

#define SMEM_SWIZZLE_128B(byte_offset) \
    ((byte_offset) ^ (((byte_offset) >> 3) & 0x70))

typedef unsigned short ush;

// weight-buffer offsets (ush elements; each a multiple of its row size)
#define O_W2  0         // [256 n, 512 k]  bf16 hi+lo
#define O_IN  131072    // [1024 n, 256 k] bf16 hi+lo
#define O_OUT 393216    // [256 n, 512 k]  fp16 hi
#define O_Q   524288    // [256 n, 256 k]  fp16 hi
#define O_K   589824    // [256 n, 256 k]  fp16 hi

// ===========================================================================
// Scratch (device globals)
// ===========================================================================
__device__ float g_pe    [NNODE * PDIM];
__device__ float g_M1c   [HDIM * HDIM];
__device__ float g_M2c   [HDIM * HDIM];
__device__ float g_Wcat1 [HDIM * 512];
__device__ float g_bias1 [512];
__device__ float g_cvec1 [HDIM];
__device__ float g_cvec2 [HDIM];
__device__ float g_precat[NNODE * 512];
__device__ float g_x     [(size_t)NT * HDIM];
__device__ float g_x2    [(size_t)NT * HDIM];
__device__ float g_xp    [(size_t)NT * 1024];
__device__ float g_d1    [(size_t)NT * DTR];
__device__ float g_Bm    [(size_t)NT * SDIM];
__device__ float g_Cm    [(size_t)NT * SDIM];
__device__ float g_dwT   [DTR * EDIM];
__device__ float g_bwT   [DTR * EDIM];
__device__ float g_cwT   [DTR * EDIM];
// adjacency neighbor lists (built once, used by both aggregations)
__device__ int   g_ncnt  [NT];
__device__ int   g_nidx  [(size_t)NT * NNODE];
// 16-bit operand buffers
__device__ ush g_c1h[(size_t)NT * 512];
__device__ ush g_c1l[(size_t)NT * 512];
__device__ ush g_xh [(size_t)NT * HDIM];
__device__ ush g_xl [(size_t)NT * HDIM];
__device__ ush g_qh [(size_t)NT * HDIM];
__device__ ush g_kh [(size_t)NT * HDIM];
__device__ ush g_wh [786432];
__device__ ush g_wl [786432];

__device__ __forceinline__ void bsplit16(float v, ush& h, ush& l) {  // bf16
    __nv_bfloat16 hh = __float2bfloat16(v);
    __nv_bfloat16 ll = __float2bfloat16(v - __bfloat162float(hh));
    h = *reinterpret_cast<ush*>(&hh);
    l = *reinterpret_cast<ush*>(&ll);
}
__device__ __forceinline__ void fsplit16(float v, ush& h, ush& l) {  // fp16
    __half hh = __float2half(v);
    __half ll = __float2half(v - __half2float(hh));
    h = *reinterpret_cast<ush*>(&hh);
    l = *reinterpret_cast<ush*>(&ll);
}
__device__ __forceinline__ ush f2h16(float v) {
    __half hh = __float2half(v);
    return *reinterpret_cast<ush*>(&hh);
}

// ===========================================================================
// Fast math (FMA-pipe exp)
// ===========================================================================
__device__ __forceinline__ float fast_exp(float x) {
    x = fminf(fmaxf(x, -87.0f), 87.0f);
    float y = x * 1.44269504088896340736f;
    float t = y + 12582912.0f;
    int   e = __float_as_int(t) - 0x4B400000;
    float r = t - 12582912.0f;
    float f = (y - r) * 0.69314718055994530942f;
    float p = 1.3888889e-3f;
    p = fmaf(p, f, 8.3333333e-3f);
    p = fmaf(p, f, 4.1666668e-2f);
    p = fmaf(p, f, 1.6666667e-1f);
    p = fmaf(p, f, 0.5f);
    p = fmaf(p, f, 1.0f);
    p = fmaf(p, f, 1.0f);
    float s = __int_as_float((e + 127) << 23);
    return p * s;
}
__device__ __forceinline__ float fast_sigmoid(float x) {
    return 1.0f / (1.0f + fast_exp(-x));
}
__device__ __forceinline__ float fast_softplus(float x) {
    if (x > 20.0f) return x;
    return log1pf(fast_exp(x));
}

// ===========================================================================
// Warp MMA / async-copy primitives (baseline sm_80+ only)
// ===========================================================================
__device__ __forceinline__ uint32_t smem_u32(const void* p) {
    uint32_t a;
    asm("{ .reg .u64 t; cvta.to.shared.u64 t, %1; cvt.u32.u64 %0, t; }"
        : "=r"(a) : "l"(p));
    return a;
}
__device__ __forceinline__ void ldsm_x4(uint32_t* r, uint32_t addr) {
    asm volatile("ldmatrix.sync.aligned.m8n8.x4.shared.b16 {%0,%1,%2,%3}, [%4];"
        : "=r"(r[0]), "=r"(r[1]), "=r"(r[2]), "=r"(r[3]) : "r"(addr));
}
__device__ __forceinline__ void mma_bf16(float* c, const uint32_t* a,
                                         uint32_t b0, uint32_t b1) {
    asm volatile(
        "mma.sync.aligned.m16n8k16.row.col.f32.bf16.bf16.f32 "
        "{%0,%1,%2,%3}, {%4,%5,%6,%7}, {%8,%9}, {%0,%1,%2,%3};"
        : "+f"(c[0]), "+f"(c[1]), "+f"(c[2]), "+f"(c[3])
        : "r"(a[0]), "r"(a[1]), "r"(a[2]), "r"(a[3]), "r"(b0), "r"(b1));
}
__device__ __forceinline__ void mma_f16(float* c, const uint32_t* a,
                                        uint32_t b0, uint32_t b1) {
    asm volatile(
        "mma.sync.aligned.m16n8k16.row.col.f32.f16.f16.f32 "
        "{%0,%1,%2,%3}, {%4,%5,%6,%7}, {%8,%9}, {%0,%1,%2,%3};"
        : "+f"(c[0]), "+f"(c[1]), "+f"(c[2]), "+f"(c[3])
        : "r"(a[0]), "r"(a[1]), "r"(a[2]), "r"(a[3]), "r"(b0), "r"(b1));
}
__device__ __forceinline__ void cp_async16(uint32_t saddr, const void* gaddr) {
    asm volatile("cp.async.cg.shared.global [%0], [%1], 16;"
        :: "r"(saddr), "l"(gaddr));
}
#define CP_COMMIT()  asm volatile("cp.async.commit_group;" ::: "memory")
#define CP_WAIT(n)   asm volatile("cp.async.wait_group %0;" :: "n"(n) : "memory")

// ===========================================================================
// HMMA split GEMM (identical to validated R12/R13 kernel)
// mode 0: fp32 out (+bias); mode 1: score head; mode 2: fp16 out (hi only);
// mode 3: out_proj fused residual+transpose+fp16; mode 4: +bias+cnt*cvec
// ===========================================================================
template<int FTAIL>
__global__ void __launch_bounds__(128, 2) gemm_k(
    const ush* __restrict__ Ah, const ush* __restrict__ Al,
    const ush* __restrict__ Bh, const ush* __restrict__ Bl,
    const float* __restrict__ bias, const float* __restrict__ addrow,
    const int* __restrict__ cntp,
    void* __restrict__ out1, void* __restrict__ out2,
    const float* __restrict__ gb_ptr,
    int K, int Nc, int mode, int nseg,
    size_t aBatch, size_t bBatch, size_t cBatch)
{
    extern __shared__ __align__(16) char smem[];
    const uint32_t sb = smem_u32(smem);
    const int tid = threadIdx.x;
    const int wid = tid >> 5, lane = tid & 31;
    const int wm = wid & 1, wn = wid >> 1;

    const size_t zA = (size_t)blockIdx.z * aBatch;
    const size_t zB = (size_t)blockIdx.z * bBatch;
    const ush* Aseg[3] = { Ah + zA, Al + zA, Ah + zA };
    const ush* Bseg[3] = { Bh + zB, Bh + zB, Bl + zB };

    const int m0 = blockIdx.y * 128, n0 = blockIdx.x * 128;
    const int ksub = K >> 6;
    const int nk = nseg * ksub;

    float acc[4][8][4];
#pragma unroll
    for (int i = 0; i < 4; i++)
#pragma unroll
        for (int j = 0; j < 8; j++)
#pragma unroll
            for (int r = 0; r < 4; r++) acc[i][j][r] = 0.0f;

    const int a_r = ((lane >> 3) & 1) * 8 + (lane & 7);
    const int a_c = ((lane >> 4) & 1) * 8;
    const int b_n = ((lane >> 4) & 1) * 8 + (lane & 7);
    const int b_k = ((lane >> 3) & 1) * 8;

    auto load_tile = [&](const ush* g, int row0, int k0, uint32_t sdst) {
#pragma unroll
        for (int j = 0; j < 8; j++) {
            int c = tid + j * 128;          // 0..1023
            int row = c >> 3, ch = c & 7;
            const void* gp = g + (size_t)(row0 + row) * K + k0 + ch * 8;
            uint32_t sp = sdst + SMEM_SWIZZLE_128B((uint32_t)(row * 128 + ch * 16));
            cp_async16(sp, gp);
        }
    };

    load_tile(Aseg[0], m0, 0, sb);
    load_tile(Bseg[0], n0, 0, sb + 16384);
    CP_COMMIT();

    for (int i = 0; i < nk; i++) {
        int b = i & 1;
        if (i + 1 < nk) {
            int seg = (i + 1) / ksub;
            int k0 = ((i + 1) - seg * ksub) << 6;
            uint32_t sd = sb + (uint32_t)(b ^ 1) * 32768u;
            load_tile(Aseg[seg], m0, k0, sd);
            load_tile(Bseg[seg], n0, k0, sd + 16384);
            CP_COMMIT();
            CP_WAIT(1);
        } else {
            CP_COMMIT();
            CP_WAIT(0);
        }
        __syncthreads();

        uint32_t abase = sb + (uint32_t)b * 32768u;
        uint32_t bbase = abase + 16384u;
#pragma unroll
        for (int ks = 0; ks < 4; ks++) {
            uint32_t afr[4][4];
#pragma unroll
            for (int mi = 0; mi < 4; mi++) {
                int row = wm * 64 + mi * 16 + a_r;
                int col = ks * 16 + a_c;
                ldsm_x4(afr[mi],
                        abase + SMEM_SWIZZLE_128B((uint32_t)(row * 128 + col * 2)));
            }
            uint32_t bfr[4][4];
#pragma unroll
            for (int j = 0; j < 4; j++) {
                int n = wn * 64 + j * 16 + b_n;
                int kc = ks * 16 + b_k;
                ldsm_x4(bfr[j],
                        bbase + SMEM_SWIZZLE_128B((uint32_t)(n * 128 + kc * 2)));
            }
#pragma unroll
            for (int mi = 0; mi < 4; mi++)
#pragma unroll
                for (int ni = 0; ni < 8; ni++) {
                    const uint32_t* bs = bfr[ni >> 1];
                    if (FTAIL)
                        mma_f16(acc[mi][ni], afr[mi],
                                bs[(ni & 1) * 2], bs[(ni & 1) * 2 + 1]);
                    else
                        mma_bf16(acc[mi][ni], afr[mi],
                                 bs[(ni & 1) * 2], bs[(ni & 1) * 2 + 1]);
                }
        }
        __syncthreads();
    }

    // ---------------- epilogue ----------------
    const int rg = lane >> 2;
    const int cg = (lane & 3) * 2;
#pragma unroll
    for (int mi = 0; mi < 4; mi++) {
#pragma unroll
        for (int ni = 0; ni < 8; ni++) {
            float* c = acc[mi][ni];
            int gr0 = m0 + wm * 64 + mi * 16 + rg;
            int gc  = n0 + wn * 64 + ni * 8 + cg;
            if (mode == 0) {
                float* C = (float*)out1;
                float b0 = bias ? bias[gc] : 0.0f;
                float b1 = bias ? bias[gc + 1] : 0.0f;
                *(float2*)(C + (size_t)gr0 * Nc + gc)       = {c[0] + b0, c[1] + b1};
                *(float2*)(C + (size_t)(gr0 + 8) * Nc + gc) = {c[2] + b0, c[3] + b1};
            } else if (mode == 1) {
                float gb = *gb_ptr;
                float* P = (float*)out1 + (size_t)blockIdx.z * cBatch;
                float* L = (float*)out2 + (size_t)blockIdx.z * cBatch;
                float l0 = c[0] * 0.0625f + gb, l1 = c[1] * 0.0625f + gb;
                float l2 = c[2] * 0.0625f + gb, l3 = c[3] * 0.0625f + gb;
                *(float2*)(L + (size_t)gr0 * Nc + gc)       = {l0, l1};
                *(float2*)(L + (size_t)(gr0 + 8) * Nc + gc) = {l2, l3};
                *(float2*)(P + (size_t)gr0 * Nc + gc)       =
                    {fast_sigmoid(l0), fast_sigmoid(l1)};
                *(float2*)(P + (size_t)(gr0 + 8) * Nc + gc) =
                    {fast_sigmoid(l2), fast_sigmoid(l3)};
            } else if (mode == 2) {  // fp16 output (hi only)
                ush* H = (ush*)out1;
                H[(size_t)gr0 * Nc + gc]           = f2h16(c[0]);
                H[(size_t)gr0 * Nc + gc + 1]       = f2h16(c[1]);
                H[(size_t)(gr0 + 8) * Nc + gc]     = f2h16(c[2]);
                H[(size_t)(gr0 + 8) * Nc + gc + 1] = f2h16(c[3]);
            } else if (mode == 3) {  // out_proj fused residual+transpose+fp16
                float* O = (float*)out1;
                ush*   H = (ush*)out2;
                int t0 = gr0 & 31, nn0 = gr0 >> 5;
                size_t d0 = ((size_t)t0 * NNODE + nn0) * Nc + gc;
                float v0 = c[0] + bias[gc]     + addrow[d0];
                float v1 = c[1] + bias[gc + 1] + addrow[d0 + 1];
                *(float2*)(O + d0) = {v0, v1};
                H[d0] = f2h16(v0); H[d0 + 1] = f2h16(v1);
                int t1 = (gr0 + 8) & 31, nn1 = (gr0 + 8) >> 5;
                size_t d1 = ((size_t)t1 * NNODE + nn1) * Nc + gc;
                float v2 = c[2] + bias[gc]     + addrow[d1];
                float v3 = c[3] + bias[gc + 1] + addrow[d1 + 1];
                *(float2*)(O + d1) = {v2, v3};
                H[d1] = f2h16(v2); H[d1 + 1] = f2h16(v3);
            } else {  // mode 4: + bias + cnt[row]*cvec[col]
                float* C = (float*)out1;
                float cn0 = (float)cntp[gr0];
                float cn1 = (float)cntp[gr0 + 8];
                float b0 = bias[gc]     + cn0 * addrow[gc];
                float b1 = bias[gc + 1] + cn0 * addrow[gc + 1];
                float b2 = bias[gc]     + cn1 * addrow[gc];
                float b3 = bias[gc + 1] + cn1 * addrow[gc + 1];
                *(float2*)(C + (size_t)gr0 * Nc + gc)       = {c[0] + b0, c[1] + b1};
                *(float2*)(C + (size_t)(gr0 + 8) * Nc + gc) = {c[2] + b2, c[3] + b3};
            }
        }
    }
}

// ===========================================================================
// Small SIMT SGEMM (exact fp32): C = A[M,K]@B[K,N] + bias
// ===========================================================================
__global__ void __launch_bounds__(256) sgemm_nn(
    const float* __restrict__ A, const float* __restrict__ B,
    const float* __restrict__ bias, float* __restrict__ C,
    int M, int Nc, int K)
{
    __shared__ float As[8][128];
    __shared__ float Bs[8][128];
    int tid = threadIdx.x;
    int bx = blockIdx.x, by = blockIdx.y;
    int tx = tid & 15, ty = tid >> 4;
    int arow = tid >> 1, acol = (tid & 1) * 4;
    int brow = tid >> 5, bcol = (tid & 31) * 4;
    const float* Ab = A + (size_t)by * 128 * K;
    const float* Bb = B + (size_t)bx * 128;
    float acc[8][8] = {};
    for (int k0 = 0; k0 < K; k0 += 8) {
        float4 av = *(const float4*)(Ab + (size_t)arow * K + k0 + acol);
        As[acol + 0][arow] = av.x; As[acol + 1][arow] = av.y;
        As[acol + 2][arow] = av.z; As[acol + 3][arow] = av.w;
        *(float4*)&Bs[brow][bcol] =
            *(const float4*)(Bb + (size_t)(k0 + brow) * Nc + bcol);
        __syncthreads();
#pragma unroll
        for (int kk = 0; kk < 8; kk++) {
            float4 a0 = *(float4*)&As[kk][ty * 8];
            float4 a1 = *(float4*)&As[kk][ty * 8 + 4];
            float4 b0 = *(float4*)&Bs[kk][tx * 8];
            float4 b1 = *(float4*)&Bs[kk][tx * 8 + 4];
            float ar[8] = {a0.x, a0.y, a0.z, a0.w, a1.x, a1.y, a1.z, a1.w};
            float br[8] = {b0.x, b0.y, b0.z, b0.w, b1.x, b1.y, b1.z, b1.w};
#pragma unroll
            for (int i = 0; i < 8; i++)
#pragma unroll
                for (int j = 0; j < 8; j++)
                    acc[i][j] = fmaf(ar[i], br[j], acc[i][j]);
        }
        __syncthreads();
    }
#pragma unroll
    for (int i = 0; i < 8; i++) {
        int r = by * 128 + ty * 8 + i;
#pragma unroll
        for (int j = 0; j < 8; j += 4) {
            int c = bx * 128 + tx * 8 + j;
            float4 v;
            v.x = acc[i][j] + bias[c];         v.y = acc[i][j + 1] + bias[c + 1];
            v.z = acc[i][j + 2] + bias[c + 2]; v.w = acc[i][j + 3] + bias[c + 3];
            *(float4*)(C + (size_t)r * Nc + c) = v;
        }
    }
}

// fold2: z=0 -> M1c = msg1_w @ W1bot; z=1 -> M2c = msg2_w @ W2bot  (256^3 each)
__global__ void __launch_bounds__(256) fold2_kernel(
    const float* __restrict__ m1w, const float* __restrict__ W1bot,
    const float* __restrict__ m2w, const float* __restrict__ W2bot)
{
    const float* A = blockIdx.z ? m2w : m1w;
    const float* B = blockIdx.z ? W2bot : W1bot;
    float* C = blockIdx.z ? g_M2c : g_M1c;
    __shared__ float As[8][128];
    __shared__ float Bs[8][128];
    int tid = threadIdx.x;
    int bx = blockIdx.x, by = blockIdx.y;
    int tx = tid & 15, ty = tid >> 4;
    int arow = tid >> 1, acol = (tid & 1) * 4;
    int brow = tid >> 5, bcol = (tid & 31) * 4;
    const float* Ab = A + (size_t)by * 128 * 256;
    const float* Bb = B + (size_t)bx * 128;
    float acc[8][8] = {};
    for (int k0 = 0; k0 < 256; k0 += 8) {
        float4 av = *(const float4*)(Ab + (size_t)arow * 256 + k0 + acol);
        As[acol + 0][arow] = av.x; As[acol + 1][arow] = av.y;
        As[acol + 2][arow] = av.z; As[acol + 3][arow] = av.w;
        *(float4*)&Bs[brow][bcol] =
            *(const float4*)(Bb + (size_t)(k0 + brow) * 256 + bcol);
        __syncthreads();
#pragma unroll
        for (int kk = 0; kk < 8; kk++) {
            float4 a0 = *(float4*)&As[kk][ty * 8];
            float4 a1 = *(float4*)&As[kk][ty * 8 + 4];
            float4 b0 = *(float4*)&Bs[kk][tx * 8];
            float4 b1 = *(float4*)&Bs[kk][tx * 8 + 4];
            float ar[8] = {a0.x, a0.y, a0.z, a0.w, a1.x, a1.y, a1.z, a1.w};
            float br[8] = {b0.x, b0.y, b0.z, b0.w, b1.x, b1.y, b1.z, b1.w};
#pragma unroll
            for (int i = 0; i < 8; i++)
#pragma unroll
                for (int j = 0; j < 8; j++)
                    acc[i][j] = fmaf(ar[i], br[j], acc[i][j]);
        }
        __syncthreads();
    }
#pragma unroll
    for (int i = 0; i < 8; i++) {
        int r = by * 128 + ty * 8 + i;
#pragma unroll
        for (int j = 0; j < 8; j += 4) {
            int c = bx * 128 + tx * 8 + j;
            float4 v = {acc[i][j], acc[i][j + 1], acc[i][j + 2], acc[i][j + 3]};
            *(float4*)(C + (size_t)r * 256 + c) = v;
        }
    }
}

// ===========================================================================
// Elementwise / helper kernels
// ===========================================================================
__global__ void pe_kernel() {
    int n = blockIdx.x;
    int i = threadIdx.x;  // 0..127
    float div = expf((float)(2 * i) * (-0.03597867333f));
    float ang = (float)n * div;
    g_pe[n * PDIM + 2 * i]     = sinf(ang);
    g_pe[n * PDIM + 2 * i + 1] = cosf(ang);
}

// cvec[h] = sum_k b[k] * Wbot[k*256+h]
__global__ void cvec_kernel(const float* __restrict__ b1,
                            const float* __restrict__ W1bot,
                            const float* __restrict__ b2,
                            const float* __restrict__ W2bot)
{
    int h = threadIdx.x;
    const float* b = blockIdx.x ? b2 : b1;
    const float* W = blockIdx.x ? W2bot : W1bot;
    float acc = 0.0f;
    for (int k = 0; k < 256; k++)
        acc = fmaf(b[k], W[k * 256 + h], acc);
    (blockIdx.x ? g_cvec2 : g_cvec1)[h] = acc;
}

// ONE launch: all weight transposes+splits + Wcat1/bias1 build.
// Segments (linear id):
//  [0,        65536)  upd2top -> O_W2 (ktot 512, koff 0,   bf16 hi+lo)
//  [65536,   131072)  M2c     -> O_W2 (ktot 512, koff 256, bf16 hi+lo)
//  [131072,  393216)  in_w    -> O_IN (ktot 256, bf16 hi+lo)
//  [393216,  524288)  out_w   -> O_OUT(ktot 512, fp16 hi)
//  [524288,  589824)  q_w     -> O_Q  (ktot 256, fp16 hi)
//  [589824,  655360)  k_w     -> O_K  (ktot 256, fp16 hi)
//  [655360,  786432)  Wcat1[k*512+n] = n<256 ? upd1top[k*256+n] : M1c[k*256+n-256]
//  [786432,  786944)  bias1[n] = n<256 ? upd1_b[n] : 0
__global__ void split_all(const float* __restrict__ upd2_w,
                          const float* __restrict__ in_w,
                          const float* __restrict__ out_w,
                          const float* __restrict__ q_w,
                          const float* __restrict__ k_w,
                          const float* __restrict__ upd1_w,
                          const float* __restrict__ upd1_b)
{
    int id = blockIdx.x * 256 + threadIdx.x;
    if (id < 65536) {
        int k = id >> 8, n = id & 255;                 // upd2top [256,256]
        ush h, l; bsplit16(upd2_w[id], h, l);
        size_t d = O_W2 + (size_t)n * 512 + k;
        g_wh[d] = h; g_wl[d] = l;
    } else if (id < 131072) {
        int i = id - 65536;
        int k = i >> 8, n = i & 255;                   // M2c [256,256]
        ush h, l; bsplit16(g_M2c[i], h, l);
        size_t d = O_W2 + (size_t)n * 512 + 256 + k;
        g_wh[d] = h; g_wl[d] = l;
    } else if (id < 393216) {
        int i = id - 131072;                           // in_w [256,1024]
        int k = i >> 10, n = i & 1023;
        ush h, l; bsplit16(in_w[i], h, l);
        size_t d = O_IN + (size_t)n * 256 + k;
        g_wh[d] = h; g_wl[d] = l;
    } else if (id < 524288) {
        int i = id - 393216;                           // out_w [512,256]
        int k = i >> 8, n = i & 255;
        g_wh[O_OUT + (size_t)n * 512 + k] = f2h16(out_w[i]);
    } else if (id < 589824) {
        int i = id - 524288;                           // q_w [256,256]
        int k = i >> 8, n = i & 255;
        g_wh[O_Q + (size_t)n * 256 + k] = f2h16(q_w[i]);
    } else if (id < 655360) {
        int i = id - 589824;                           // k_w [256,256]
        int k = i >> 8, n = i & 255;
        g_wh[O_K + (size_t)n * 256 + k] = f2h16(k_w[i]);
    } else if (id < 786432) {
        int i = id - 655360;                           // Wcat1 [256,512]
        int k = i >> 9, n = i & 511;
        g_Wcat1[i] = (n < 256) ? upd1_w[k * 256 + n] : g_M1c[k * 256 + (n - 256)];
    } else if (id < 786944) {
        int n = id - 786432;
        g_bias1[n] = (n < 256) ? upd1_b[n] : 0.0f;
    }
}

// Build adjacency neighbor lists once
__global__ void build_nbr(const float* __restrict__ adj) {
    int i = blockIdx.x, t = blockIdx.y;
    size_t row = (size_t)t * NNODE + i;
    const float4* a4 = (const float4*)(adj + row * NNODE);
    __shared__ int s_idx[NNODE];
    __shared__ int s_cnt;
    if (threadIdx.x == 0) s_cnt = 0;
    __syncthreads();
    float4 v = a4[threadIdx.x];
    int j0 = threadIdx.x * 4;
    if (v.x != 0.0f) s_idx[atomicAdd(&s_cnt, 1)] = j0;
    if (v.y != 0.0f) s_idx[atomicAdd(&s_cnt, 1)] = j0 + 1;
    if (v.z != 0.0f) s_idx[atomicAdd(&s_cnt, 1)] = j0 + 2;
    if (v.w != 0.0f) s_idx[atomicAdd(&s_cnt, 1)] = j0 + 3;
    __syncthreads();
    int cnt = s_cnt;
    if (threadIdx.x == 0) g_ncnt[row] = cnt;
    for (int p = threadIdx.x; p < cnt; p += 256)
        g_nidx[row * NNODE + p] = s_idx[p];
}

// Layer-1 FUSED: gather(precat hi-half) + precat lo-half + cnt*cvec1
// + relu + LN -> g_x fp32 and bf16 split into c1h/c1l cols [0,256)
__global__ void gather1_fused(const float* __restrict__ gam,
                              const float* __restrict__ bet)
{
    int i = blockIdx.x, t = blockIdx.y;
    size_t row = (size_t)t * NNODE + i;
    int cnt = g_ncnt[row];
    const int* idx = g_nidx + row * NNODE;
    int h = threadIdx.x;
    float acc = g_precat[(size_t)i * 512 + h] + (float)cnt * g_cvec1[h];
    for (int p = 0; p < cnt; p++)
        acc += g_precat[(size_t)idx[p] * 512 + 256 + h];
    float v = fmaxf(acc, 0.0f);
    float s = v, q = v * v;
#pragma unroll
    for (int o = 16; o > 0; o >>= 1) {
        s += __shfl_xor_sync(0xffffffffu, s, o);
        q += __shfl_xor_sync(0xffffffffu, q, o);
    }
    __shared__ float ss[8], qq[8];
    __shared__ float s_mu, s_rstd;
    int w = h >> 5;
    if ((h & 31) == 0) { ss[w] = s; qq[w] = q; }
    __syncthreads();
    if (h == 0) {
        float S = 0, QQ = 0;
        for (int j = 0; j < 8; j++) { S += ss[j]; QQ += qq[j]; }
        float mu = S * (1.0f / 256.0f);
        float var = QQ * (1.0f / 256.0f) - mu * mu;
        s_mu = mu; s_rstd = rsqrtf(var + 1e-5f);
    }
    __syncthreads();
    float o = (v - s_mu) * s_rstd * gam[h] + bet[h];
    g_x[row * HDIM + h] = o;
    ush hh, ll; bsplit16(o, hh, ll);
    g_c1h[row * 512 + h] = hh;
    g_c1l[row * 512 + h] = ll;
}

// Layer-2 gather of x (per-t), bf16 split into c1h/c1l cols [256,512)
__global__ void gather2(void) {
    int i = blockIdx.x, t = blockIdx.y;
    size_t row = (size_t)t * NNODE + i;
    int cnt = g_ncnt[row];
    const int* idx = g_nidx + row * NNODE;
    int h = threadIdx.x;
    const float* mb = g_x + (size_t)t * NNODE * HDIM;
    float acc = 0.0f;
    for (int p = 0; p < cnt; p++)
        acc += mb[(size_t)idx[p] * HDIM + h];
    ush hi, lo; bsplit16(acc, hi, lo);
    g_c1h[row * 512 + 256 + h] = hi;
    g_c1l[row * 512 + 256 + h] = lo;
}

// FUSED: relu+LN2 (writes x2 fp32, t-major) then Mamba pre-LN of the result
// (writes bf16 splits xh/xl, n-major). In-place on g_x2.
__global__ void ln2_mamba(const float* __restrict__ g2, const float* __restrict__ b2,
                          const float* __restrict__ gm, const float* __restrict__ bm)
{
    int rin = blockIdx.x;              // t*N + n
    int tid = threadIdx.x;
    int t = rin >> 10, n = rin & 1023;
    __shared__ float ss[8], qq[8];
    __shared__ float s_mu, s_rstd;
    int w = tid >> 5;

    float v = fmaxf(g_x2[(size_t)rin * HDIM + tid], 0.0f);
    float s = v, q = v * v;
#pragma unroll
    for (int o = 16; o > 0; o >>= 1) {
        s += __shfl_xor_sync(0xffffffffu, s, o);
        q += __shfl_xor_sync(0xffffffffu, q, o);
    }
    if ((tid & 31) == 0) { ss[w] = s; qq[w] = q; }
    __syncthreads();
    if (tid == 0) {
        float S = 0, QQ = 0;
        for (int i = 0; i < 8; i++) { S += ss[i]; QQ += qq[i]; }
        float mu = S * (1.0f / 256.0f);
        float var = QQ * (1.0f / 256.0f) - mu * mu;
        s_mu = mu; s_rstd = rsqrtf(var + 1e-5f);
    }
    __syncthreads();
    float o = (v - s_mu) * s_rstd * g2[tid] + b2[tid];
    g_x2[(size_t)rin * HDIM + tid] = o;
    __syncthreads();

    // second LN (mamba pre-norm) on o
    float s2 = o, q2 = o * o;
#pragma unroll
    for (int of = 16; of > 0; of >>= 1) {
        s2 += __shfl_xor_sync(0xffffffffu, s2, of);
        q2 += __shfl_xor_sync(0xffffffffu, q2, of);
    }
    if ((tid & 31) == 0) { ss[w] = s2; qq[w] = q2; }
    __syncthreads();
    if (tid == 0) {
        float S = 0, QQ = 0;
        for (int i = 0; i < 8; i++) { S += ss[i]; QQ += qq[i]; }
        float mu = S * (1.0f / 256.0f);
        float var = QQ * (1.0f / 256.0f) - mu * mu;
        s_mu = mu; s_rstd = rsqrtf(var + 1e-5f);
    }
    __syncthreads();
    float o2 = (o - s_mu) * s_rstd * gm[tid] + bm[tid];
    size_t dst = ((size_t)n * TSTEP + t) * HDIM + tid;
    ush h, l; bsplit16(o2, h, l);
    g_xh[dst] = h; g_xl[dst] = l;
}

__global__ void transpose_w3(const float* __restrict__ dw,
                             const float* __restrict__ bw,
                             const float* __restrict__ cw)
{
    int id = blockIdx.x * 256 + threadIdx.x;  // 8192
    if (id < EDIM * DTR) {
        int k = id >> 4, n = id & 15;
        g_dwT[n * EDIM + k] = dw[id];
        g_bwT[n * EDIM + k] = bw[id];
        g_cwT[n * EDIM + k] = cw[id];
    }
}

// proj3 with inline silu on xp
__global__ void proj3_kernel(const float* __restrict__ db,
                             const float* __restrict__ bb,
                             const float* __restrict__ cb)
{
    int r = blockIdx.x * 16 + (threadIdx.x >> 4);
    int n = threadIdx.x & 15;
    const float4* a4 = (const float4*)(g_xp + (size_t)r * 1024);
    const float4* d4 = (const float4*)(g_dwT + n * EDIM);
    const float4* b4 = (const float4*)(g_bwT + n * EDIM);
    const float4* c4 = (const float4*)(g_cwT + n * EDIM);
    float ad = 0, ab = 0, ac = 0;
#pragma unroll 4
    for (int k = 0; k < EDIM / 4; k++) {
        float4 a = a4[k];
        a.x *= fast_sigmoid(a.x); a.y *= fast_sigmoid(a.y);
        a.z *= fast_sigmoid(a.z); a.w *= fast_sigmoid(a.w);
        float4 d = d4[k], b = b4[k], c = c4[k];
        ad = fmaf(a.x, d.x, fmaf(a.y, d.y, fmaf(a.z, d.z, fmaf(a.w, d.w, ad))));
        ab = fmaf(a.x, b.x, fmaf(a.y, b.y, fmaf(a.z, b.z, fmaf(a.w, b.w, ab))));
        ac = fmaf(a.x, c.x, fmaf(a.y, c.y, fmaf(a.z, c.z, fmaf(a.w, c.w, ac))));
    }
    size_t o = (size_t)r * 16 + n;
    g_d1[o] = ad + db[n];
    g_Bm[o] = ab + bb[n];
    g_Cm[o] = ac + cb[n];
}

// Selective scan with fused delta computation and inline silu on xp;
// writes y as fp16 splits into g_c1h/g_c1l
__global__ void __launch_bounds__(512) scan_kernel(
    const float* __restrict__ A_log, const float* __restrict__ D_vec,
    const float* __restrict__ dtw, const float* __restrict__ dtb)
{
    int n = blockIdx.x;
    int e = threadIdx.x;
    float A[SDIM], h[SDIM], wreg[DTR];
#pragma unroll
    for (int s = 0; s < SDIM; s++) {
        A[s] = -fast_exp(A_log[e * SDIM + s]);
        h[s] = 0.0f;
    }
#pragma unroll
    for (int k = 0; k < DTR; k++)
        wreg[k] = dtw[k * EDIM + e];
    float dbv = dtb[e];
    float Dv = D_vec[e];
    __shared__ float sbv[TSTEP * SDIM], scv[TSTEP * SDIM], sd1[TSTEP * DTR];
    sbv[e] = g_Bm[(size_t)n * (TSTEP * SDIM) + e];
    scv[e] = g_Cm[(size_t)n * (TSTEP * SDIM) + e];
    sd1[e] = g_d1[(size_t)n * (TSTEP * DTR) + e];
    __syncthreads();
    for (int t = 0; t < TSTEP; t++) {
        size_t r = (size_t)n * TSTEP + t;
        const float* sb = sbv + t * SDIM;
        const float* sc = scv + t * SDIM;
        const float* d1 = sd1 + t * DTR;
        float dacc = dbv;
#pragma unroll
        for (int k = 0; k < DTR; k++)
            dacc = fmaf(d1[k], wreg[k], dacc);
        float dt = fast_softplus(dacc);
        float xv = g_xp[r * 1024 + e];
        float xt = xv * fast_sigmoid(xv);
        float dx = dt * xt;
        float yv = 0.0f;
#pragma unroll
        for (int s = 0; s < SDIM; s++) {
            h[s] = fmaf(fast_exp(dt * A[s]), h[s], dx * sb[s]);
            yv   = fmaf(sc[s], h[s], yv);
        }
        yv += xt * Dv;
        float g = g_xp[r * 1024 + EDIM + e];
        yv *= g * fast_sigmoid(g);
        ush hi, lo; fsplit16(yv, hi, lo);
        g_c1h[r * EDIM + e] = hi;
        g_c1l[r * EDIM + e] = lo;
    }
}

// ===========================================================================
// Host launch
// ===========================================================================
#define GEMM_SMEM 65536

extern "C" void kernel_launch(void* const* d_in, const int* in_sizes, int n_in,
                              void* d_out, int out_size)
{
    const float* adj     = (const float*)d_in[0];
    const float* msg1_w  = (const float*)d_in[1];
    const float* msg1_b  = (const float*)d_in[2];
    const float* upd1_w  = (const float*)d_in[3];
    const float* upd1_b  = (const float*)d_in[4];
    const float* ln1_g   = (const float*)d_in[5];
    const float* ln1_b   = (const float*)d_in[6];
    const float* msg2_w  = (const float*)d_in[7];
    const float* msg2_b  = (const float*)d_in[8];
    const float* upd2_w  = (const float*)d_in[9];
    const float* upd2_b  = (const float*)d_in[10];
    const float* ln2_g   = (const float*)d_in[11];
    const float* ln2_b   = (const float*)d_in[12];
    const float* mbln_g  = (const float*)d_in[13];
    const float* mbln_b  = (const float*)d_in[14];
    const float* in_w    = (const float*)d_in[15];
    const float* in_b    = (const float*)d_in[16];
    const float* delta_w = (const float*)d_in[17];
    const float* delta_b = (const float*)d_in[18];
    const float* dt_w    = (const float*)d_in[19];
    const float* dt_b    = (const float*)d_in[20];
    const float* Bp_w    = (const float*)d_in[21];
    const float* Bp_b    = (const float*)d_in[22];
    const float* Cp_w    = (const float*)d_in[23];
    const float* Cp_b    = (const float*)d_in[24];
    const float* A_log   = (const float*)d_in[25];
    const float* D_vec   = (const float*)d_in[26];
    const float* out_w   = (const float*)d_in[27];
    const float* out_b   = (const float*)d_in[28];
    const float* q_w     = (const float*)d_in[29];
    const float* k_w     = (const float*)d_in[30];
    const float* gate_b  = (const float*)d_in[31];

    float* out    = (float*)d_out;
    float* outs   = out;                                    // [T,N,H]
    float* probs  = out + (size_t)TSTEP * NNODE * HDIM;     // [T,N,N]
    float* logits = probs + (size_t)TSTEP * NNODE * NNODE;  // [T,N,N]

    cudaFuncSetAttribute(gemm_k<0>, cudaFuncAttributeMaxDynamicSharedMemorySize,
                         GEMM_SMEM);
    cudaFuncSetAttribute(gemm_k<1>, cudaFuncAttributeMaxDynamicSharedMemorySize,
                         GEMM_SMEM);

    float *pe_, *Wcat1_, *bias1_, *cvec2_, *precat_, *x2_, *xp_;
    int* cnt_;
    ush *c1h_, *c1l_, *xh_, *xl_, *qh_, *kh_, *wh_, *wl_;
    cudaGetSymbolAddress((void**)&pe_,     g_pe);
    cudaGetSymbolAddress((void**)&Wcat1_,  g_Wcat1);
    cudaGetSymbolAddress((void**)&bias1_,  g_bias1);
    cudaGetSymbolAddress((void**)&cvec2_,  g_cvec2);
    cudaGetSymbolAddress((void**)&precat_, g_precat);
    cudaGetSymbolAddress((void**)&x2_,     g_x2);
    cudaGetSymbolAddress((void**)&xp_,     g_xp);
    cudaGetSymbolAddress((void**)&cnt_,    g_ncnt);
    cudaGetSymbolAddress((void**)&c1h_,    g_c1h);
    cudaGetSymbolAddress((void**)&c1l_,    g_c1l);
    cudaGetSymbolAddress((void**)&xh_,     g_xh);
    cudaGetSymbolAddress((void**)&xl_,     g_xl);
    cudaGetSymbolAddress((void**)&qh_,     g_qh);
    cudaGetSymbolAddress((void**)&kh_,     g_kh);
    cudaGetSymbolAddress((void**)&wh_,     g_wh);
    cudaGetSymbolAddress((void**)&wl_,     g_wl);

    const float* W1bot = upd1_w + 256 * 256;
    const float* W2bot = upd2_w + 256 * 256;

    // 1. prologue: PE, neighbor lists, folds (1 launch), cvec, splits (1),
    //    combined pre-GEMM (precat = pe @ [upd1top | M1c] + [b1|0])
    pe_kernel<<<NNODE, 128>>>();
    build_nbr<<<dim3(NNODE, TSTEP), 256>>>(adj);
    fold2_kernel<<<dim3(2, 2, 2), 256>>>(msg1_w, W1bot, msg2_w, W2bot);
    cvec_kernel<<<2, 256>>>(msg1_b, W1bot, msg2_b, W2bot);
    split_all<<<3074, 256>>>(upd2_w, in_w, out_w, q_w, k_w, upd1_w, upd1_b);
    sgemm_nn<<<dim3(4, 8), 256>>>(pe_, Wcat1_, bias1_, precat_, NNODE, 512, 256);
    // 2. layer 1: fused gather+relu+LN (no NT GEMM)
    gather1_fused<<<dim3(NNODE, TSTEP), 256>>>(ln1_g, ln1_b);
    // 3. layer 2: gather x; combined [x|aggx] @ [W2top; M2c] GEMM (mode 4)
    gather2<<<dim3(NNODE, TSTEP), 256>>>();
    gemm_k<0><<<dim3(2, NT / 128), 128, GEMM_SMEM>>>(
        c1h_, c1l_, wh_ + O_W2, wl_ + O_W2, upd2_b, cvec2_, cnt_, x2_,
        nullptr, nullptr, 512, 256, 4, 3, 0, 0, 0);
    // 4. fused relu+LN2 + mamba pre-LN; then in_proj GEMM
    ln2_mamba<<<NT, 256>>>(ln2_g, ln2_b, mbln_g, mbln_b);
    gemm_k<0><<<dim3(8, NT / 128), 128, GEMM_SMEM>>>(
        xh_, xl_, wh_ + O_IN, wl_ + O_IN, in_b, nullptr, nullptr, xp_,
        nullptr, nullptr, 256, 1024, 0, 3, 0, 0, 0);
    // 5. small projections (inline silu)
    transpose_w3<<<(EDIM * DTR + 255) / 256, 256>>>(delta_w, Bp_w, Cp_w);
    proj3_kernel<<<NT / 16, 256>>>(delta_b, Bp_b, Cp_b);
    // 6. scan (fused delta + silu; writes y fp16 splits into c1h/c1l)
    scan_kernel<<<NNODE, EDIM>>>(A_log, D_vec, dt_w, dt_b);
    // 7. out projection (fp16 2-pass) with fused residual+transpose epilogue
    gemm_k<1><<<dim3(2, NT / 128), 128, GEMM_SMEM>>>(
        c1h_, c1l_, wh_ + O_OUT, nullptr, out_b, x2_, nullptr, outs, xh_,
        nullptr, 512, 256, 3, 2, 0, 0, 0);
    // 8. q/k GEMMs (fp16 1-pass), then score head (fp16 1-pass)
    gemm_k<1><<<dim3(2, NT / 128), 128, GEMM_SMEM>>>(
        xh_, nullptr, wh_ + O_Q, nullptr, nullptr, nullptr, nullptr, qh_,
        nullptr, nullptr, 256, 256, 2, 1, 0, 0, 0);
    gemm_k<1><<<dim3(2, NT / 128), 128, GEMM_SMEM>>>(
        xh_, nullptr, wh_ + O_K, nullptr, nullptr, nullptr, nullptr, kh_,
        nullptr, nullptr, 256, 256, 2, 1, 0, 0, 0);
    gemm_k<1><<<dim3(8, 8, TSTEP), 128, GEMM_SMEM>>>(
        qh_, nullptr, kh_, nullptr, nullptr, nullptr, nullptr, probs, logits,
        gate_b, 256, 1024, 1, 1,
        (size_t)NNODE * HDIM, (size_t)NNODE * HDIM, (size_t)NNODE * NNODE);
}

// round 16
// speedup vs baseline: 1.0692x; 1.0162x over previous
#include <cuda_runtime.h>
#include <cuda_fp16.h>
#include <cuda_bf16.h>
#include <cstdint>

// Problem constants
#define NNODE 1024
#define TSTEP 32
#define HDIM  256
#define PDIM  256
#define EDIM  512
#define DTR   16
#define SDIM  16
#define NT    (NNODE * TSTEP)   // 32768

#define SMEM_SWIZZLE_128B(byte_offset) \
    ((byte_offset) ^ (((byte_offset) >> 3) & 0x70))

typedef unsigned short ush;

// weight-buffer offsets (ush elements)
#define O_W2  0         // [256 n, 512 k]  bf16 hi+lo
#define O_IN  131072    // [1024 n, 256 k] bf16 hi+lo
#define O_OUT 393216    // [256 n, 512 k]  fp16 hi
#define O_QK  524288    // [512 n, 256 k]  fp16 hi (q rows 0-255, k rows 256-511)

// ===========================================================================
// Scratch (device globals)
// ===========================================================================
__device__ float g_pe    [NNODE * PDIM];
__device__ float g_M1c   [HDIM * HDIM];
__device__ float g_M2c   [HDIM * HDIM];
__device__ float g_Wcat1 [HDIM * 512];
__device__ float g_bias1 [512];
__device__ float g_cvec1 [HDIM];
__device__ float g_cvec2 [HDIM];
__device__ float g_precat[NNODE * 512];
__device__ float g_x     [(size_t)NT * HDIM];
__device__ float g_x2    [(size_t)NT * HDIM];
__device__ float g_xp    [(size_t)NT * 1024];
__device__ float g_d1    [(size_t)NT * DTR];
__device__ float g_Bm    [(size_t)NT * SDIM];
__device__ float g_Cm    [(size_t)NT * SDIM];
__device__ float g_dwT   [DTR * EDIM];
__device__ float g_bwT   [DTR * EDIM];
__device__ float g_cwT   [DTR * EDIM];
// adjacency neighbor lists (built once, used by both aggregations)
__device__ int   g_ncnt  [NT];
__device__ int   g_nidx  [(size_t)NT * NNODE];
// 16-bit operand buffers (c1h doubles as the qk buffer after out_proj)
__device__ ush g_c1h[(size_t)NT * 512];
__device__ ush g_c1l[(size_t)NT * 512];
__device__ ush g_xh [(size_t)NT * HDIM];
__device__ ush g_xl [(size_t)NT * HDIM];
__device__ ush g_wh [786432];
__device__ ush g_wl [786432];

__device__ __forceinline__ void bsplit16(float v, ush& h, ush& l) {  // bf16
    __nv_bfloat16 hh = __float2bfloat16(v);
    __nv_bfloat16 ll = __float2bfloat16(v - __bfloat162float(hh));
    h = *reinterpret_cast<ush*>(&hh);
    l = *reinterpret_cast<ush*>(&ll);
}
__device__ __forceinline__ void fsplit16(float v, ush& h, ush& l) {  // fp16
    __half hh = __float2half(v);
    __half ll = __float2half(v - __half2float(hh));
    h = *reinterpret_cast<ush*>(&hh);
    l = *reinterpret_cast<ush*>(&ll);
}
__device__ __forceinline__ ush f2h16(float v) {
    __half hh = __float2half(v);
    return *reinterpret_cast<ush*>(&hh);
}

// ===========================================================================
// Fast math (FMA-pipe exp)
// ===========================================================================
__device__ __forceinline__ float fast_exp(float x) {
    x = fminf(fmaxf(x, -87.0f), 87.0f);
    float y = x * 1.44269504088896340736f;
    float t = y + 12582912.0f;
    int   e = __float_as_int(t) - 0x4B400000;
    float r = t - 12582912.0f;
    float f = (y - r) * 0.69314718055994530942f;
    float p = 1.3888889e-3f;
    p = fmaf(p, f, 8.3333333e-3f);
    p = fmaf(p, f, 4.1666668e-2f);
    p = fmaf(p, f, 1.6666667e-1f);
    p = fmaf(p, f, 0.5f);
    p = fmaf(p, f, 1.0f);
    p = fmaf(p, f, 1.0f);
    float s = __int_as_float((e + 127) << 23);
    return p * s;
}
__device__ __forceinline__ float fast_sigmoid(float x) {
    return 1.0f / (1.0f + fast_exp(-x));
}
__device__ __forceinline__ float fast_softplus(float x) {
    if (x > 20.0f) return x;
    return log1pf(fast_exp(x));
}

// ===========================================================================
// Warp MMA / async-copy primitives (baseline sm_80+ only)
// ===========================================================================
__device__ __forceinline__ uint32_t smem_u32(const void* p) {
    uint32_t a;
    asm("{ .reg .u64 t; cvta.to.shared.u64 t, %1; cvt.u32.u64 %0, t; }"
        : "=r"(a) : "l"(p));
    return a;
}
__device__ __forceinline__ void ldsm_x4(uint32_t* r, uint32_t addr) {
    asm volatile("ldmatrix.sync.aligned.m8n8.x4.shared.b16 {%0,%1,%2,%3}, [%4];"
        : "=r"(r[0]), "=r"(r[1]), "=r"(r[2]), "=r"(r[3]) : "r"(addr));
}
__device__ __forceinline__ void mma_bf16(float* c, const uint32_t* a,
                                         uint32_t b0, uint32_t b1) {
    asm volatile(
        "mma.sync.aligned.m16n8k16.row.col.f32.bf16.bf16.f32 "
        "{%0,%1,%2,%3}, {%4,%5,%6,%7}, {%8,%9}, {%0,%1,%2,%3};"
        : "+f"(c[0]), "+f"(c[1]), "+f"(c[2]), "+f"(c[3])
        : "r"(a[0]), "r"(a[1]), "r"(a[2]), "r"(a[3]), "r"(b0), "r"(b1));
}
__device__ __forceinline__ void mma_f16(float* c, const uint32_t* a,
                                        uint32_t b0, uint32_t b1) {
    asm volatile(
        "mma.sync.aligned.m16n8k16.row.col.f32.f16.f16.f32 "
        "{%0,%1,%2,%3}, {%4,%5,%6,%7}, {%8,%9}, {%0,%1,%2,%3};"
        : "+f"(c[0]), "+f"(c[1]), "+f"(c[2]), "+f"(c[3])
        : "r"(a[0]), "r"(a[1]), "r"(a[2]), "r"(a[3]), "r"(b0), "r"(b1));
}
__device__ __forceinline__ void cp_async16(uint32_t saddr, const void* gaddr) {
    asm volatile("cp.async.cg.shared.global [%0], [%1], 16;"
        :: "r"(saddr), "l"(gaddr));
}
#define CP_COMMIT()  asm volatile("cp.async.commit_group;" ::: "memory")
#define CP_WAIT(n)   asm volatile("cp.async.wait_group %0;" :: "n"(n) : "memory")

// ===========================================================================
// HMMA split GEMM (validated R12-R15 core; + per-operand row strides)
// mode 0: fp32 out (+bias); mode 1: score head; mode 2: fp16 out (hi only);
// mode 3: out_proj fused residual+transpose+fp16; mode 4: +bias+cnt*cvec
// ===========================================================================
template<int FTAIL>
__global__ void __launch_bounds__(128, 2) gemm_k(
    const ush* __restrict__ Ah, const ush* __restrict__ Al,
    const ush* __restrict__ Bh, const ush* __restrict__ Bl,
    const float* __restrict__ bias, const float* __restrict__ addrow,
    const int* __restrict__ cntp,
    void* __restrict__ out1, void* __restrict__ out2,
    const float* __restrict__ gb_ptr,
    int K, int Nc, int mode, int nseg, int aStride, int bStride,
    size_t aBatch, size_t bBatch, size_t cBatch)
{
    extern __shared__ __align__(16) char smem[];
    const uint32_t sb = smem_u32(smem);
    const int tid = threadIdx.x;
    const int wid = tid >> 5, lane = tid & 31;
    const int wm = wid & 1, wn = wid >> 1;

    const size_t zA = (size_t)blockIdx.z * aBatch;
    const size_t zB = (size_t)blockIdx.z * bBatch;
    const ush* Aseg[3] = { Ah + zA, Al + zA, Ah + zA };
    const ush* Bseg[3] = { Bh + zB, Bh + zB, Bl + zB };

    const int m0 = blockIdx.y * 128, n0 = blockIdx.x * 128;
    const int ksub = K >> 6;
    const int nk = nseg * ksub;

    float acc[4][8][4];
#pragma unroll
    for (int i = 0; i < 4; i++)
#pragma unroll
        for (int j = 0; j < 8; j++)
#pragma unroll
            for (int r = 0; r < 4; r++) acc[i][j][r] = 0.0f;

    const int a_r = ((lane >> 3) & 1) * 8 + (lane & 7);
    const int a_c = ((lane >> 4) & 1) * 8;
    const int b_n = ((lane >> 4) & 1) * 8 + (lane & 7);
    const int b_k = ((lane >> 3) & 1) * 8;

    auto load_tile = [&](const ush* g, int row0, int k0, int stride,
                         uint32_t sdst) {
#pragma unroll
        for (int j = 0; j < 8; j++) {
            int c = tid + j * 128;          // 0..1023
            int row = c >> 3, ch = c & 7;
            const void* gp = g + (size_t)(row0 + row) * stride + k0 + ch * 8;
            uint32_t sp = sdst + SMEM_SWIZZLE_128B((uint32_t)(row * 128 + ch * 16));
            cp_async16(sp, gp);
        }
    };

    load_tile(Aseg[0], m0, 0, aStride, sb);
    load_tile(Bseg[0], n0, 0, bStride, sb + 16384);
    CP_COMMIT();

    for (int i = 0; i < nk; i++) {
        int b = i & 1;
        if (i + 1 < nk) {
            int seg = (i + 1) / ksub;
            int k0 = ((i + 1) - seg * ksub) << 6;
            uint32_t sd = sb + (uint32_t)(b ^ 1) * 32768u;
            load_tile(Aseg[seg], m0, k0, aStride, sd);
            load_tile(Bseg[seg], n0, k0, bStride, sd + 16384);
            CP_COMMIT();
            CP_WAIT(1);
        } else {
            CP_COMMIT();
            CP_WAIT(0);
        }
        __syncthreads();

        uint32_t abase = sb + (uint32_t)b * 32768u;
        uint32_t bbase = abase + 16384u;
#pragma unroll
        for (int ks = 0; ks < 4; ks++) {
            uint32_t afr[4][4];
#pragma unroll
            for (int mi = 0; mi < 4; mi++) {
                int row = wm * 64 + mi * 16 + a_r;
                int col = ks * 16 + a_c;
                ldsm_x4(afr[mi],
                        abase + SMEM_SWIZZLE_128B((uint32_t)(row * 128 + col * 2)));
            }
            uint32_t bfr[4][4];
#pragma unroll
            for (int j = 0; j < 4; j++) {
                int n = wn * 64 + j * 16 + b_n;
                int kc = ks * 16 + b_k;
                ldsm_x4(bfr[j],
                        bbase + SMEM_SWIZZLE_128B((uint32_t)(n * 128 + kc * 2)));
            }
#pragma unroll
            for (int mi = 0; mi < 4; mi++)
#pragma unroll
                for (int ni = 0; ni < 8; ni++) {
                    const uint32_t* bs = bfr[ni >> 1];
                    if (FTAIL)
                        mma_f16(acc[mi][ni], afr[mi],
                                bs[(ni & 1) * 2], bs[(ni & 1) * 2 + 1]);
                    else
                        mma_bf16(acc[mi][ni], afr[mi],
                                 bs[(ni & 1) * 2], bs[(ni & 1) * 2 + 1]);
                }
        }
        __syncthreads();
    }

    // ---------------- epilogue ----------------
    const int rg = lane >> 2;
    const int cg = (lane & 3) * 2;
#pragma unroll
    for (int mi = 0; mi < 4; mi++) {
#pragma unroll
        for (int ni = 0; ni < 8; ni++) {
            float* c = acc[mi][ni];
            int gr0 = m0 + wm * 64 + mi * 16 + rg;
            int gc  = n0 + wn * 64 + ni * 8 + cg;
            if (mode == 0) {
                float* C = (float*)out1;
                float b0 = bias ? bias[gc] : 0.0f;
                float b1 = bias ? bias[gc + 1] : 0.0f;
                *(float2*)(C + (size_t)gr0 * Nc + gc)       = {c[0] + b0, c[1] + b1};
                *(float2*)(C + (size_t)(gr0 + 8) * Nc + gc) = {c[2] + b0, c[3] + b1};
            } else if (mode == 1) {
                float gb = *gb_ptr;
                float* P = (float*)out1 + (size_t)blockIdx.z * cBatch;
                float* L = (float*)out2 + (size_t)blockIdx.z * cBatch;
                float l0 = c[0] * 0.0625f + gb, l1 = c[1] * 0.0625f + gb;
                float l2 = c[2] * 0.0625f + gb, l3 = c[3] * 0.0625f + gb;
                *(float2*)(L + (size_t)gr0 * Nc + gc)       = {l0, l1};
                *(float2*)(L + (size_t)(gr0 + 8) * Nc + gc) = {l2, l3};
                *(float2*)(P + (size_t)gr0 * Nc + gc)       =
                    {fast_sigmoid(l0), fast_sigmoid(l1)};
                *(float2*)(P + (size_t)(gr0 + 8) * Nc + gc) =
                    {fast_sigmoid(l2), fast_sigmoid(l3)};
            } else if (mode == 2) {  // fp16 output (hi only)
                ush* H = (ush*)out1;
                H[(size_t)gr0 * Nc + gc]           = f2h16(c[0]);
                H[(size_t)gr0 * Nc + gc + 1]       = f2h16(c[1]);
                H[(size_t)(gr0 + 8) * Nc + gc]     = f2h16(c[2]);
                H[(size_t)(gr0 + 8) * Nc + gc + 1] = f2h16(c[3]);
            } else if (mode == 3) {  // out_proj fused residual+transpose+fp16
                float* O = (float*)out1;
                ush*   H = (ush*)out2;
                int t0 = gr0 & 31, nn0 = gr0 >> 5;
                size_t d0 = ((size_t)t0 * NNODE + nn0) * Nc + gc;
                float v0 = c[0] + bias[gc]     + addrow[d0];
                float v1 = c[1] + bias[gc + 1] + addrow[d0 + 1];
                *(float2*)(O + d0) = {v0, v1};
                H[d0] = f2h16(v0); H[d0 + 1] = f2h16(v1);
                int t1 = (gr0 + 8) & 31, nn1 = (gr0 + 8) >> 5;
                size_t d1 = ((size_t)t1 * NNODE + nn1) * Nc + gc;
                float v2 = c[2] + bias[gc]     + addrow[d1];
                float v3 = c[3] + bias[gc + 1] + addrow[d1 + 1];
                *(float2*)(O + d1) = {v2, v3};
                H[d1] = f2h16(v2); H[d1 + 1] = f2h16(v3);
            } else {  // mode 4: + bias + cnt[row]*cvec[col]
                float* C = (float*)out1;
                float cn0 = (float)cntp[gr0];
                float cn1 = (float)cntp[gr0 + 8];
                float b0 = bias[gc]     + cn0 * addrow[gc];
                float b1 = bias[gc + 1] + cn0 * addrow[gc + 1];
                float b2 = bias[gc]     + cn1 * addrow[gc];
                float b3 = bias[gc + 1] + cn1 * addrow[gc + 1];
                *(float2*)(C + (size_t)gr0 * Nc + gc)       = {c[0] + b0, c[1] + b1};
                *(float2*)(C + (size_t)(gr0 + 8) * Nc + gc) = {c[2] + b2, c[3] + b3};
            }
        }
    }
}

// ===========================================================================
// Small SIMT SGEMM (exact fp32): C = A[M,K]@B[K,N] + bias
// ===========================================================================
__global__ void __launch_bounds__(256) sgemm_nn(
    const float* __restrict__ A, const float* __restrict__ B,
    const float* __restrict__ bias, float* __restrict__ C,
    int M, int Nc, int K)
{
    __shared__ float As[8][128];
    __shared__ float Bs[8][128];
    int tid = threadIdx.x;
    int bx = blockIdx.x, by = blockIdx.y;
    int tx = tid & 15, ty = tid >> 4;
    int arow = tid >> 1, acol = (tid & 1) * 4;
    int brow = tid >> 5, bcol = (tid & 31) * 4;
    const float* Ab = A + (size_t)by * 128 * K;
    const float* Bb = B + (size_t)bx * 128;
    float acc[8][8] = {};
    for (int k0 = 0; k0 < K; k0 += 8) {
        float4 av = *(const float4*)(Ab + (size_t)arow * K + k0 + acol);
        As[acol + 0][arow] = av.x; As[acol + 1][arow] = av.y;
        As[acol + 2][arow] = av.z; As[acol + 3][arow] = av.w;
        *(float4*)&Bs[brow][bcol] =
            *(const float4*)(Bb + (size_t)(k0 + brow) * Nc + bcol);
        __syncthreads();
#pragma unroll
        for (int kk = 0; kk < 8; kk++) {
            float4 a0 = *(float4*)&As[kk][ty * 8];
            float4 a1 = *(float4*)&As[kk][ty * 8 + 4];
            float4 b0 = *(float4*)&Bs[kk][tx * 8];
            float4 b1 = *(float4*)&Bs[kk][tx * 8 + 4];
            float ar[8] = {a0.x, a0.y, a0.z, a0.w, a1.x, a1.y, a1.z, a1.w};
            float br[8] = {b0.x, b0.y, b0.z, b0.w, b1.x, b1.y, b1.z, b1.w};
#pragma unroll
            for (int i = 0; i < 8; i++)
#pragma unroll
                for (int j = 0; j < 8; j++)
                    acc[i][j] = fmaf(ar[i], br[j], acc[i][j]);
        }
        __syncthreads();
    }
#pragma unroll
    for (int i = 0; i < 8; i++) {
        int r = by * 128 + ty * 8 + i;
#pragma unroll
        for (int j = 0; j < 8; j += 4) {
            int c = bx * 128 + tx * 8 + j;
            float4 v;
            v.x = acc[i][j] + bias[c];         v.y = acc[i][j + 1] + bias[c + 1];
            v.z = acc[i][j + 2] + bias[c + 2]; v.w = acc[i][j + 3] + bias[c + 3];
            *(float4*)(C + (size_t)r * Nc + c) = v;
        }
    }
}

// fold2: z=0 -> M1c = msg1_w @ W1bot; z=1 -> M2c = msg2_w @ W2bot  (256^3 each)
__global__ void __launch_bounds__(256) fold2_kernel(
    const float* __restrict__ m1w, const float* __restrict__ W1bot,
    const float* __restrict__ m2w, const float* __restrict__ W2bot)
{
    const float* A = blockIdx.z ? m2w : m1w;
    const float* B = blockIdx.z ? W2bot : W1bot;
    float* C = blockIdx.z ? g_M2c : g_M1c;
    __shared__ float As[8][128];
    __shared__ float Bs[8][128];
    int tid = threadIdx.x;
    int bx = blockIdx.x, by = blockIdx.y;
    int tx = tid & 15, ty = tid >> 4;
    int arow = tid >> 1, acol = (tid & 1) * 4;
    int brow = tid >> 5, bcol = (tid & 31) * 4;
    const float* Ab = A + (size_t)by * 128 * 256;
    const float* Bb = B + (size_t)bx * 128;
    float acc[8][8] = {};
    for (int k0 = 0; k0 < 256; k0 += 8) {
        float4 av = *(const float4*)(Ab + (size_t)arow * 256 + k0 + acol);
        As[acol + 0][arow] = av.x; As[acol + 1][arow] = av.y;
        As[acol + 2][arow] = av.z; As[acol + 3][arow] = av.w;
        *(float4*)&Bs[brow][bcol] =
            *(const float4*)(Bb + (size_t)(k0 + brow) * 256 + bcol);
        __syncthreads();
#pragma unroll
        for (int kk = 0; kk < 8; kk++) {
            float4 a0 = *(float4*)&As[kk][ty * 8];
            float4 a1 = *(float4*)&As[kk][ty * 8 + 4];
            float4 b0 = *(float4*)&Bs[kk][tx * 8];
            float4 b1 = *(float4*)&Bs[kk][tx * 8 + 4];
            float ar[8] = {a0.x, a0.y, a0.z, a0.w, a1.x, a1.y, a1.z, a1.w};
            float br[8] = {b0.x, b0.y, b0.z, b0.w, b1.x, b1.y, b1.z, b1.w};
#pragma unroll
            for (int i = 0; i < 8; i++)
#pragma unroll
                for (int j = 0; j < 8; j++)
                    acc[i][j] = fmaf(ar[i], br[j], acc[i][j]);
        }
        __syncthreads();
    }
#pragma unroll
    for (int i = 0; i < 8; i++) {
        int r = by * 128 + ty * 8 + i;
#pragma unroll
        for (int j = 0; j < 8; j += 4) {
            int c = bx * 128 + tx * 8 + j;
            float4 v = {acc[i][j], acc[i][j + 1], acc[i][j + 2], acc[i][j + 3]};
            *(float4*)(C + (size_t)r * 256 + c) = v;
        }
    }
}

// ===========================================================================
// Elementwise / helper kernels
// ===========================================================================
__global__ void pe_kernel() {
    int n = blockIdx.x;
    int i = threadIdx.x;  // 0..127
    float div = expf((float)(2 * i) * (-0.03597867333f));
    float ang = (float)n * div;
    g_pe[n * PDIM + 2 * i]     = sinf(ang);
    g_pe[n * PDIM + 2 * i + 1] = cosf(ang);
}

// cvec[h] = sum_k b[k] * Wbot[k*256+h]; grid (2,8), 8 threads per output
__global__ void cvec_kernel(const float* __restrict__ b1,
                            const float* __restrict__ W1bot,
                            const float* __restrict__ b2,
                            const float* __restrict__ W2bot)
{
    int h = blockIdx.y * 32 + (threadIdx.x >> 3);
    int l8 = threadIdx.x & 7;
    const float* b = blockIdx.x ? b2 : b1;
    const float* W = blockIdx.x ? W2bot : W1bot;
    float acc = 0.0f;
    for (int k = l8; k < 256; k += 8)
        acc = fmaf(b[k], W[k * 256 + h], acc);
#pragma unroll
    for (int o = 4; o > 0; o >>= 1)
        acc += __shfl_down_sync(0xffffffffu, acc, o);
    if (l8 == 0)
        (blockIdx.x ? g_cvec2 : g_cvec1)[h] = acc;
}

// ONE launch: all weight transposes+splits + Wcat1/bias1 build.
__global__ void split_all(const float* __restrict__ upd2_w,
                          const float* __restrict__ in_w,
                          const float* __restrict__ out_w,
                          const float* __restrict__ q_w,
                          const float* __restrict__ k_w,
                          const float* __restrict__ upd1_w,
                          const float* __restrict__ upd1_b)
{
    int id = blockIdx.x * 256 + threadIdx.x;
    if (id < 65536) {
        int k = id >> 8, n = id & 255;                 // upd2top [256,256]
        ush h, l; bsplit16(upd2_w[id], h, l);
        size_t d = O_W2 + (size_t)n * 512 + k;
        g_wh[d] = h; g_wl[d] = l;
    } else if (id < 131072) {
        int i = id - 65536;
        int k = i >> 8, n = i & 255;                   // M2c [256,256]
        ush h, l; bsplit16(g_M2c[i], h, l);
        size_t d = O_W2 + (size_t)n * 512 + 256 + k;
        g_wh[d] = h; g_wl[d] = l;
    } else if (id < 393216) {
        int i = id - 131072;                           // in_w [256,1024]
        int k = i >> 10, n = i & 1023;
        ush h, l; bsplit16(in_w[i], h, l);
        size_t d = O_IN + (size_t)n * 256 + k;
        g_wh[d] = h; g_wl[d] = l;
    } else if (id < 524288) {
        int i = id - 393216;                           // out_w [512,256]
        int k = i >> 8, n = i & 255;
        g_wh[O_OUT + (size_t)n * 512 + k] = f2h16(out_w[i]);
    } else if (id < 589824) {
        int i = id - 524288;                           // q_w [256,256] -> rows 0-255
        int k = i >> 8, n = i & 255;
        g_wh[O_QK + (size_t)n * 256 + k] = f2h16(q_w[i]);
    } else if (id < 655360) {
        int i = id - 589824;                           // k_w [256,256] -> rows 256-511
        int k = i >> 8, n = i & 255;
        g_wh[O_QK + (size_t)(n + 256) * 256 + k] = f2h16(k_w[i]);
    } else if (id < 786432) {
        int i = id - 655360;                           // Wcat1 [256,512]
        int k = i >> 9, n = i & 511;
        g_Wcat1[i] = (n < 256) ? upd1_w[k * 256 + n] : g_M1c[k * 256 + (n - 256)];
    } else if (id < 786944) {
        int n = id - 786432;
        g_bias1[n] = (n < 256) ? upd1_b[n] : 0.0f;
    }
}

// Build adjacency neighbor lists once; 4 rows per block for MLP
__global__ void build_nbr(const float* __restrict__ adj) {
    int base = blockIdx.x * 4;       // 4 consecutive flat rows (t*N + i)
    __shared__ int s_idx[4][NNODE];
    __shared__ int s_cnt[4];
    if (threadIdx.x < 4) s_cnt[threadIdx.x] = 0;
    __syncthreads();
    float4 v[4];
#pragma unroll
    for (int r = 0; r < 4; r++)
        v[r] = ((const float4*)(adj + (size_t)(base + r) * NNODE))[threadIdx.x];
    int j0 = threadIdx.x * 4;
#pragma unroll
    for (int r = 0; r < 4; r++) {
        if (v[r].x != 0.0f) s_idx[r][atomicAdd(&s_cnt[r], 1)] = j0;
        if (v[r].y != 0.0f) s_idx[r][atomicAdd(&s_cnt[r], 1)] = j0 + 1;
        if (v[r].z != 0.0f) s_idx[r][atomicAdd(&s_cnt[r], 1)] = j0 + 2;
        if (v[r].w != 0.0f) s_idx[r][atomicAdd(&s_cnt[r], 1)] = j0 + 3;
    }
    __syncthreads();
#pragma unroll
    for (int r = 0; r < 4; r++) {
        size_t row = base + r;
        int cnt = s_cnt[r];
        if (threadIdx.x == 0) g_ncnt[row] = cnt;
        for (int p = threadIdx.x; p < cnt; p += 256)
            g_nidx[row * NNODE + p] = s_idx[r][p];
    }
}

// Layer-1 FUSED: gather(precat hi-half) + precat lo-half + cnt*cvec1
// + relu + LN -> g_x fp32 and bf16 split into c1h/c1l cols [0,256)
__global__ void gather1_fused(const float* __restrict__ gam,
                              const float* __restrict__ bet)
{
    int i = blockIdx.x, t = blockIdx.y;
    size_t row = (size_t)t * NNODE + i;
    int cnt = g_ncnt[row];
    const int* idx = g_nidx + row * NNODE;
    int h = threadIdx.x;
    float acc = g_precat[(size_t)i * 512 + h] + (float)cnt * g_cvec1[h];
    for (int p = 0; p < cnt; p++)
        acc += g_precat[(size_t)idx[p] * 512 + 256 + h];
    float v = fmaxf(acc, 0.0f);
    float s = v, q = v * v;
#pragma unroll
    for (int o = 16; o > 0; o >>= 1) {
        s += __shfl_xor_sync(0xffffffffu, s, o);
        q += __shfl_xor_sync(0xffffffffu, q, o);
    }
    __shared__ float ss[8], qq[8];
    __shared__ float s_mu, s_rstd;
    int w = h >> 5;
    if ((h & 31) == 0) { ss[w] = s; qq[w] = q; }
    __syncthreads();
    if (h == 0) {
        float S = 0, QQ = 0;
        for (int j = 0; j < 8; j++) { S += ss[j]; QQ += qq[j]; }
        float mu = S * (1.0f / 256.0f);
        float var = QQ * (1.0f / 256.0f) - mu * mu;
        s_mu = mu; s_rstd = rsqrtf(var + 1e-5f);
    }
    __syncthreads();
    float o = (v - s_mu) * s_rstd * gam[h] + bet[h];
    g_x[row * HDIM + h] = o;
    ush hh, ll; bsplit16(o, hh, ll);
    g_c1h[row * 512 + h] = hh;
    g_c1l[row * 512 + h] = ll;
}

// Layer-2 gather of x (per-t), bf16 split into c1h/c1l cols [256,512)
__global__ void gather2(void) {
    int i = blockIdx.x, t = blockIdx.y;
    size_t row = (size_t)t * NNODE + i;
    int cnt = g_ncnt[row];
    const int* idx = g_nidx + row * NNODE;
    int h = threadIdx.x;
    const float* mb = g_x + (size_t)t * NNODE * HDIM;
    float acc = 0.0f;
    for (int p = 0; p < cnt; p++)
        acc += mb[(size_t)idx[p] * HDIM + h];
    ush hi, lo; bsplit16(acc, hi, lo);
    g_c1h[row * 512 + 256 + h] = hi;
    g_c1l[row * 512 + 256 + h] = lo;
}

// FUSED: relu+LN2 (writes x2 fp32, t-major) then Mamba pre-LN of the result
// (writes bf16 splits xh/xl, n-major). In-place on g_x2.
__global__ void ln2_mamba(const float* __restrict__ g2, const float* __restrict__ b2,
                          const float* __restrict__ gm, const float* __restrict__ bm)
{
    int rin = blockIdx.x;              // t*N + n
    int tid = threadIdx.x;
    int t = rin >> 10, n = rin & 1023;
    __shared__ float ss[8], qq[8];
    __shared__ float s_mu, s_rstd;
    int w = tid >> 5;

    float v = fmaxf(g_x2[(size_t)rin * HDIM + tid], 0.0f);
    float s = v, q = v * v;
#pragma unroll
    for (int o = 16; o > 0; o >>= 1) {
        s += __shfl_xor_sync(0xffffffffu, s, o);
        q += __shfl_xor_sync(0xffffffffu, q, o);
    }
    if ((tid & 31) == 0) { ss[w] = s; qq[w] = q; }
    __syncthreads();
    if (tid == 0) {
        float S = 0, QQ = 0;
        for (int i = 0; i < 8; i++) { S += ss[i]; QQ += qq[i]; }
        float mu = S * (1.0f / 256.0f);
        float var = QQ * (1.0f / 256.0f) - mu * mu;
        s_mu = mu; s_rstd = rsqrtf(var + 1e-5f);
    }
    __syncthreads();
    float o = (v - s_mu) * s_rstd * g2[tid] + b2[tid];
    g_x2[(size_t)rin * HDIM + tid] = o;
    __syncthreads();

    float s2 = o, q2 = o * o;
#pragma unroll
    for (int of = 16; of > 0; of >>= 1) {
        s2 += __shfl_xor_sync(0xffffffffu, s2, of);
        q2 += __shfl_xor_sync(0xffffffffu, q2, of);
    }
    if ((tid & 31) == 0) { ss[w] = s2; qq[w] = q2; }
    __syncthreads();
    if (tid == 0) {
        float S = 0, QQ = 0;
        for (int i = 0; i < 8; i++) { S += ss[i]; QQ += qq[i]; }
        float mu = S * (1.0f / 256.0f);
        float var = QQ * (1.0f / 256.0f) - mu * mu;
        s_mu = mu; s_rstd = rsqrtf(var + 1e-5f);
    }
    __syncthreads();
    float o2 = (o - s_mu) * s_rstd * gm[tid] + bm[tid];
    size_t dst = ((size_t)n * TSTEP + t) * HDIM + tid;
    ush h, l; bsplit16(o2, h, l);
    g_xh[dst] = h; g_xl[dst] = l;
}

__global__ void transpose_w3(const float* __restrict__ dw,
                             const float* __restrict__ bw,
                             const float* __restrict__ cw)
{
    int id = blockIdx.x * 256 + threadIdx.x;  // 8192
    if (id < EDIM * DTR) {
        int k = id >> 4, n = id & 15;
        g_dwT[n * EDIM + k] = dw[id];
        g_bwT[n * EDIM + k] = bw[id];
        g_cwT[n * EDIM + k] = cw[id];
    }
}

// proj3 with inline silu on xp
__global__ void proj3_kernel(const float* __restrict__ db,
                             const float* __restrict__ bb,
                             const float* __restrict__ cb)
{
    int r = blockIdx.x * 16 + (threadIdx.x >> 4);
    int n = threadIdx.x & 15;
    const float4* a4 = (const float4*)(g_xp + (size_t)r * 1024);
    const float4* d4 = (const float4*)(g_dwT + n * EDIM);
    const float4* b4 = (const float4*)(g_bwT + n * EDIM);
    const float4* c4 = (const float4*)(g_cwT + n * EDIM);
    float ad = 0, ab = 0, ac = 0;
#pragma unroll 4
    for (int k = 0; k < EDIM / 4; k++) {
        float4 a = a4[k];
        a.x *= fast_sigmoid(a.x); a.y *= fast_sigmoid(a.y);
        a.z *= fast_sigmoid(a.z); a.w *= fast_sigmoid(a.w);
        float4 d = d4[k], b = b4[k], c = c4[k];
        ad = fmaf(a.x, d.x, fmaf(a.y, d.y, fmaf(a.z, d.z, fmaf(a.w, d.w, ad))));
        ab = fmaf(a.x, b.x, fmaf(a.y, b.y, fmaf(a.z, b.z, fmaf(a.w, b.w, ab))));
        ac = fmaf(a.x, c.x, fmaf(a.y, c.y, fmaf(a.z, c.z, fmaf(a.w, c.w, ac))));
    }
    size_t o = (size_t)r * 16 + n;
    g_d1[o] = ad + db[n];
    g_Bm[o] = ab + bb[n];
    g_Cm[o] = ac + cb[n];
}

// Selective scan with fused delta computation and inline silu on xp;
// writes y as fp16 splits into g_c1h/g_c1l
__global__ void __launch_bounds__(512) scan_kernel(
    const float* __restrict__ A_log, const float* __restrict__ D_vec,
    const float* __restrict__ dtw, const float* __restrict__ dtb)
{
    int n = blockIdx.x;
    int e = threadIdx.x;
    float A[SDIM], h[SDIM], wreg[DTR];
#pragma unroll
    for (int s = 0; s < SDIM; s++) {
        A[s] = -fast_exp(A_log[e * SDIM + s]);
        h[s] = 0.0f;
    }
#pragma unroll
    for (int k = 0; k < DTR; k++)
        wreg[k] = dtw[k * EDIM + e];
    float dbv = dtb[e];
    float Dv = D_vec[e];
    __shared__ float sbv[TSTEP * SDIM], scv[TSTEP * SDIM], sd1[TSTEP * DTR];
    sbv[e] = g_Bm[(size_t)n * (TSTEP * SDIM) + e];
    scv[e] = g_Cm[(size_t)n * (TSTEP * SDIM) + e];
    sd1[e] = g_d1[(size_t)n * (TSTEP * DTR) + e];
    __syncthreads();
    for (int t = 0; t < TSTEP; t++) {
        size_t r = (size_t)n * TSTEP + t;
        const float* sb = sbv + t * SDIM;
        const float* sc = scv + t * SDIM;
        const float* d1 = sd1 + t * DTR;
        float dacc = dbv;
#pragma unroll
        for (int k = 0; k < DTR; k++)
            dacc = fmaf(d1[k], wreg[k], dacc);
        float dt = fast_softplus(dacc);
        float xv = g_xp[r * 1024 + e];
        float xt = xv * fast_sigmoid(xv);
        float dx = dt * xt;
        float yv = 0.0f;
#pragma unroll
        for (int s = 0; s < SDIM; s++) {
            h[s] = fmaf(fast_exp(dt * A[s]), h[s], dx * sb[s]);
            yv   = fmaf(sc[s], h[s], yv);
        }
        yv += xt * Dv;
        float g = g_xp[r * 1024 + EDIM + e];
        yv *= g * fast_sigmoid(g);
        ush hi, lo; fsplit16(yv, hi, lo);
        g_c1h[r * EDIM + e] = hi;
        g_c1l[r * EDIM + e] = lo;
    }
}

// ===========================================================================
// Host launch
// ===========================================================================
#define GEMM_SMEM 65536

extern "C" void kernel_launch(void* const* d_in, const int* in_sizes, int n_in,
                              void* d_out, int out_size)
{
    const float* adj     = (const float*)d_in[0];
    const float* msg1_w  = (const float*)d_in[1];
    const float* msg1_b  = (const float*)d_in[2];
    const float* upd1_w  = (const float*)d_in[3];
    const float* upd1_b  = (const float*)d_in[4];
    const float* ln1_g   = (const float*)d_in[5];
    const float* ln1_b   = (const float*)d_in[6];
    const float* msg2_w  = (const float*)d_in[7];
    const float* msg2_b  = (const float*)d_in[8];
    const float* upd2_w  = (const float*)d_in[9];
    const float* upd2_b  = (const float*)d_in[10];
    const float* ln2_g   = (const float*)d_in[11];
    const float* ln2_b   = (const float*)d_in[12];
    const float* mbln_g  = (const float*)d_in[13];
    const float* mbln_b  = (const float*)d_in[14];
    const float* in_w    = (const float*)d_in[15];
    const float* in_b    = (const float*)d_in[16];
    const float* delta_w = (const float*)d_in[17];
    const float* delta_b = (const float*)d_in[18];
    const float* dt_w    = (const float*)d_in[19];
    const float* dt_b    = (const float*)d_in[20];
    const float* Bp_w    = (const float*)d_in[21];
    const float* Bp_b    = (const float*)d_in[22];
    const float* Cp_w    = (const float*)d_in[23];
    const float* Cp_b    = (const float*)d_in[24];
    const float* A_log   = (const float*)d_in[25];
    const float* D_vec   = (const float*)d_in[26];
    const float* out_w   = (const float*)d_in[27];
    const float* out_b   = (const float*)d_in[28];
    const float* q_w     = (const float*)d_in[29];
    const float* k_w     = (const float*)d_in[30];
    const float* gate_b  = (const float*)d_in[31];

    float* out    = (float*)d_out;
    float* outs   = out;                                    // [T,N,H]
    float* probs  = out + (size_t)TSTEP * NNODE * HDIM;     // [T,N,N]
    float* logits = probs + (size_t)TSTEP * NNODE * NNODE;  // [T,N,N]

    cudaFuncSetAttribute(gemm_k<0>, cudaFuncAttributeMaxDynamicSharedMemorySize,
                         GEMM_SMEM);
    cudaFuncSetAttribute(gemm_k<1>, cudaFuncAttributeMaxDynamicSharedMemorySize,
                         GEMM_SMEM);

    float *pe_, *Wcat1_, *bias1_, *cvec2_, *precat_, *x2_, *xp_;
    int* cnt_;
    ush *c1h_, *c1l_, *xh_, *xl_, *wh_, *wl_;
    cudaGetSymbolAddress((void**)&pe_,     g_pe);
    cudaGetSymbolAddress((void**)&Wcat1_,  g_Wcat1);
    cudaGetSymbolAddress((void**)&bias1_,  g_bias1);
    cudaGetSymbolAddress((void**)&cvec2_,  g_cvec2);
    cudaGetSymbolAddress((void**)&precat_, g_precat);
    cudaGetSymbolAddress((void**)&x2_,     g_x2);
    cudaGetSymbolAddress((void**)&xp_,     g_xp);
    cudaGetSymbolAddress((void**)&cnt_,    g_ncnt);
    cudaGetSymbolAddress((void**)&c1h_,    g_c1h);
    cudaGetSymbolAddress((void**)&c1l_,    g_c1l);
    cudaGetSymbolAddress((void**)&xh_,     g_xh);
    cudaGetSymbolAddress((void**)&xl_,     g_xl);
    cudaGetSymbolAddress((void**)&wh_,     g_wh);
    cudaGetSymbolAddress((void**)&wl_,     g_wl);

    const float* W1bot = upd1_w + 256 * 256;
    const float* W2bot = upd2_w + 256 * 256;

    // 1. prologue
    pe_kernel<<<NNODE, 128>>>();
    build_nbr<<<NT / 4, 256>>>(adj);
    fold2_kernel<<<dim3(2, 2, 2), 256>>>(msg1_w, W1bot, msg2_w, W2bot);
    cvec_kernel<<<dim3(2, 8), 256>>>(msg1_b, W1bot, msg2_b, W2bot);
    split_all<<<3074, 256>>>(upd2_w, in_w, out_w, q_w, k_w, upd1_w, upd1_b);
    sgemm_nn<<<dim3(4, 8), 256>>>(pe_, Wcat1_, bias1_, precat_, NNODE, 512, 256);
    // 2. layer 1: fused gather+relu+LN (no NT GEMM)
    gather1_fused<<<dim3(NNODE, TSTEP), 256>>>(ln1_g, ln1_b);
    // 3. layer 2: gather x; combined [x|aggx] @ [W2top; M2c] GEMM (mode 4)
    gather2<<<dim3(NNODE, TSTEP), 256>>>();
    gemm_k<0><<<dim3(2, NT / 128), 128, GEMM_SMEM>>>(
        c1h_, c1l_, wh_ + O_W2, wl_ + O_W2, upd2_b, cvec2_, cnt_, x2_,
        nullptr, nullptr, 512, 256, 4, 3, 512, 512, 0, 0, 0);
    // 4. fused relu+LN2 + mamba pre-LN; then in_proj GEMM
    ln2_mamba<<<NT, 256>>>(ln2_g, ln2_b, mbln_g, mbln_b);
    gemm_k<0><<<dim3(8, NT / 128), 128, GEMM_SMEM>>>(
        xh_, xl_, wh_ + O_IN, wl_ + O_IN, in_b, nullptr, nullptr, xp_,
        nullptr, nullptr, 256, 1024, 0, 3, 256, 256, 0, 0, 0);
    // 5. small projections (inline silu)
    transpose_w3<<<(EDIM * DTR + 255) / 256, 256>>>(delta_w, Bp_w, Cp_w);
    proj3_kernel<<<NT / 16, 256>>>(delta_b, Bp_b, Cp_b);
    // 6. scan (fused delta + silu; writes y fp16 splits into c1h/c1l)
    scan_kernel<<<NNODE, EDIM>>>(A_log, D_vec, dt_w, dt_b);
    // 7. out projection (fp16 2-pass) with fused residual+transpose epilogue
    gemm_k<1><<<dim3(2, NT / 128), 128, GEMM_SMEM>>>(
        c1h_, c1l_, wh_ + O_OUT, nullptr, out_b, x2_, nullptr, outs, xh_,
        nullptr, 512, 256, 3, 2, 512, 512, 0, 0, 0);
    // 8. merged q+k GEMM (fp16 1-pass) into qk buffer (c1h reused, [NT,512]),
    //    then score head: A = qk[:,0:256], B = qk[:,256:512] (strided)
    gemm_k<1><<<dim3(4, NT / 128), 128, GEMM_SMEM>>>(
        xh_, nullptr, wh_ + O_QK, nullptr, nullptr, nullptr, nullptr, c1h_,
        nullptr, nullptr, 256, 512, 2, 1, 256, 256, 0, 0, 0);
    gemm_k<1><<<dim3(8, 8, TSTEP), 128, GEMM_SMEM>>>(
        c1h_, nullptr, c1h_ + 256, nullptr, nullptr, nullptr, nullptr,
        probs, logits, gate_b, 256, 1024, 1, 1, 512, 512,
        (size_t)NNODE * 512, (size_t)NNODE * 512, (size_t)NNODE * NNODE);
}

// round 17
// speedup vs baseline: 1.1183x; 1.0459x over previous
#include <cuda_runtime.h>
#include <cuda_fp16.h>
#include <cuda_bf16.h>
#include <cstdint>

// Problem constants
#define NNODE 1024
#define TSTEP 32
#define HDIM  256
#define PDIM  256
#define EDIM  512
#define DTR   16
#define SDIM  16
#define NT    (NNODE * TSTEP)   // 32768

#define SMEM_SWIZZLE_128B(byte_offset) \
    ((byte_offset) ^ (((byte_offset) >> 3) & 0x70))

typedef unsigned short ush;

// weight-buffer offsets (ush elements) — all fp16 hi now
#define O_W2  0         // [256 n, 512 k]
#define O_IN  131072    // [1024 n, 256 k]
#define O_OUT 393216    // [256 n, 512 k]
#define O_QK  524288    // [512 n, 256 k] (q rows 0-255, k rows 256-511)

// ===========================================================================
// Scratch (device globals)
// ===========================================================================
__device__ float g_pe    [NNODE * PDIM];
__device__ float g_M1c   [HDIM * HDIM];
__device__ float g_M2c   [HDIM * HDIM];
__device__ float g_Wcat1 [HDIM * 512];
__device__ float g_bias1 [512];
__device__ float g_cvec1 [HDIM];
__device__ float g_cvec2 [HDIM];
__device__ float g_precat[NNODE * 512];
__device__ float g_x     [(size_t)NT * HDIM];
__device__ float g_x2    [(size_t)NT * HDIM];
__device__ float g_xp    [(size_t)NT * 1024];
__device__ float g_d1    [(size_t)NT * DTR];
__device__ float g_Bm    [(size_t)NT * SDIM];
__device__ float g_Cm    [(size_t)NT * SDIM];
__device__ float g_dwT   [DTR * EDIM];
__device__ float g_bwT   [DTR * EDIM];
__device__ float g_cwT   [DTR * EDIM];
// adjacency neighbor lists (built once, used by both aggregations)
__device__ int   g_ncnt  [NT];
__device__ int   g_nidx  [(size_t)NT * NNODE];
// 16-bit operand buffers (fp16; c1h doubles as qk buffer after out_proj)
__device__ ush g_c1h[(size_t)NT * 512];
__device__ ush g_c1l[(size_t)NT * 512];
__device__ ush g_xh [(size_t)NT * HDIM];
__device__ ush g_xl [(size_t)NT * HDIM];
__device__ ush g_wh [786432];

__device__ __forceinline__ void fsplit16(float v, ush& h, ush& l) {  // fp16
    __half hh = __float2half(v);
    __half ll = __float2half(v - __half2float(hh));
    h = *reinterpret_cast<ush*>(&hh);
    l = *reinterpret_cast<ush*>(&ll);
}
__device__ __forceinline__ ush f2h16(float v) {
    __half hh = __float2half(v);
    return *reinterpret_cast<ush*>(&hh);
}

// ===========================================================================
// Fast math (FMA-pipe exp)
// ===========================================================================
__device__ __forceinline__ float fast_exp(float x) {
    x = fminf(fmaxf(x, -87.0f), 87.0f);
    float y = x * 1.44269504088896340736f;
    float t = y + 12582912.0f;
    int   e = __float_as_int(t) - 0x4B400000;
    float r = t - 12582912.0f;
    float f = (y - r) * 0.69314718055994530942f;
    float p = 1.3888889e-3f;
    p = fmaf(p, f, 8.3333333e-3f);
    p = fmaf(p, f, 4.1666668e-2f);
    p = fmaf(p, f, 1.6666667e-1f);
    p = fmaf(p, f, 0.5f);
    p = fmaf(p, f, 1.0f);
    p = fmaf(p, f, 1.0f);
    float s = __int_as_float((e + 127) << 23);
    return p * s;
}
__device__ __forceinline__ float fast_sigmoid(float x) {
    return 1.0f / (1.0f + fast_exp(-x));
}
__device__ __forceinline__ float fast_softplus(float x) {
    if (x > 20.0f) return x;
    return log1pf(fast_exp(x));
}

// ===========================================================================
// Warp MMA / async-copy primitives (baseline sm_80+ only)
// ===========================================================================
__device__ __forceinline__ uint32_t smem_u32(const void* p) {
    uint32_t a;
    asm("{ .reg .u64 t; cvta.to.shared.u64 t, %1; cvt.u32.u64 %0, t; }"
        : "=r"(a) : "l"(p));
    return a;
}
__device__ __forceinline__ void ldsm_x4(uint32_t* r, uint32_t addr) {
    asm volatile("ldmatrix.sync.aligned.m8n8.x4.shared.b16 {%0,%1,%2,%3}, [%4];"
        : "=r"(r[0]), "=r"(r[1]), "=r"(r[2]), "=r"(r[3]) : "r"(addr));
}
__device__ __forceinline__ void mma_f16(float* c, const uint32_t* a,
                                        uint32_t b0, uint32_t b1) {
    asm volatile(
        "mma.sync.aligned.m16n8k16.row.col.f32.f16.f16.f32 "
        "{%0,%1,%2,%3}, {%4,%5,%6,%7}, {%8,%9}, {%0,%1,%2,%3};"
        : "+f"(c[0]), "+f"(c[1]), "+f"(c[2]), "+f"(c[3])
        : "r"(a[0]), "r"(a[1]), "r"(a[2]), "r"(a[3]), "r"(b0), "r"(b1));
}
__device__ __forceinline__ void cp_async16(uint32_t saddr, const void* gaddr) {
    asm volatile("cp.async.cg.shared.global [%0], [%1], 16;"
        :: "r"(saddr), "l"(gaddr));
}
#define CP_COMMIT()  asm volatile("cp.async.commit_group;" ::: "memory")
#define CP_WAIT(n)   asm volatile("cp.async.wait_group %0;" :: "n"(n) : "memory")

// ===========================================================================
// HMMA fp16 split GEMM (validated core; per-operand row strides)
// nseg=1: Ah*Bh   nseg=2: Ah*Bh + Al*Bh   (fp32 accumulate)
// mode 0: fp32 out (+bias); mode 1: score head; mode 2: fp16 out (hi only);
// mode 3: out_proj fused residual+transpose+fp16; mode 4: +bias+cnt*cvec
// ===========================================================================
__global__ void __launch_bounds__(128, 2) gemm_k(
    const ush* __restrict__ Ah, const ush* __restrict__ Al,
    const ush* __restrict__ Bh,
    const float* __restrict__ bias, const float* __restrict__ addrow,
    const int* __restrict__ cntp,
    void* __restrict__ out1, void* __restrict__ out2,
    const float* __restrict__ gb_ptr,
    int K, int Nc, int mode, int nseg, int aStride, int bStride,
    size_t aBatch, size_t bBatch, size_t cBatch)
{
    extern __shared__ __align__(16) char smem[];
    const uint32_t sb = smem_u32(smem);
    const int tid = threadIdx.x;
    const int wid = tid >> 5, lane = tid & 31;
    const int wm = wid & 1, wn = wid >> 1;

    const size_t zA = (size_t)blockIdx.z * aBatch;
    const size_t zB = (size_t)blockIdx.z * bBatch;
    const ush* Aseg[2] = { Ah + zA, Al + zA };
    const ush* Bp = Bh + zB;

    const int m0 = blockIdx.y * 128, n0 = blockIdx.x * 128;
    const int ksub = K >> 6;
    const int nk = nseg * ksub;

    float acc[4][8][4];
#pragma unroll
    for (int i = 0; i < 4; i++)
#pragma unroll
        for (int j = 0; j < 8; j++)
#pragma unroll
            for (int r = 0; r < 4; r++) acc[i][j][r] = 0.0f;

    const int a_r = ((lane >> 3) & 1) * 8 + (lane & 7);
    const int a_c = ((lane >> 4) & 1) * 8;
    const int b_n = ((lane >> 4) & 1) * 8 + (lane & 7);
    const int b_k = ((lane >> 3) & 1) * 8;

    auto load_tile = [&](const ush* g, int row0, int k0, int stride,
                         uint32_t sdst) {
#pragma unroll
        for (int j = 0; j < 8; j++) {
            int c = tid + j * 128;          // 0..1023
            int row = c >> 3, ch = c & 7;
            const void* gp = g + (size_t)(row0 + row) * stride + k0 + ch * 8;
            uint32_t sp = sdst + SMEM_SWIZZLE_128B((uint32_t)(row * 128 + ch * 16));
            cp_async16(sp, gp);
        }
    };

    load_tile(Aseg[0], m0, 0, aStride, sb);
    load_tile(Bp, n0, 0, bStride, sb + 16384);
    CP_COMMIT();

    for (int i = 0; i < nk; i++) {
        int b = i & 1;
        if (i + 1 < nk) {
            int seg = (i + 1) / ksub;
            int k0 = ((i + 1) - seg * ksub) << 6;
            uint32_t sd = sb + (uint32_t)(b ^ 1) * 32768u;
            load_tile(Aseg[seg], m0, k0, aStride, sd);
            load_tile(Bp, n0, k0, bStride, sd + 16384);
            CP_COMMIT();
            CP_WAIT(1);
        } else {
            CP_COMMIT();
            CP_WAIT(0);
        }
        __syncthreads();

        uint32_t abase = sb + (uint32_t)b * 32768u;
        uint32_t bbase = abase + 16384u;
#pragma unroll
        for (int ks = 0; ks < 4; ks++) {
            uint32_t afr[4][4];
#pragma unroll
            for (int mi = 0; mi < 4; mi++) {
                int row = wm * 64 + mi * 16 + a_r;
                int col = ks * 16 + a_c;
                ldsm_x4(afr[mi],
                        abase + SMEM_SWIZZLE_128B((uint32_t)(row * 128 + col * 2)));
            }
            uint32_t bfr[4][4];
#pragma unroll
            for (int j = 0; j < 4; j++) {
                int n = wn * 64 + j * 16 + b_n;
                int kc = ks * 16 + b_k;
                ldsm_x4(bfr[j],
                        bbase + SMEM_SWIZZLE_128B((uint32_t)(n * 128 + kc * 2)));
            }
#pragma unroll
            for (int mi = 0; mi < 4; mi++)
#pragma unroll
                for (int ni = 0; ni < 8; ni++) {
                    const uint32_t* bs = bfr[ni >> 1];
                    mma_f16(acc[mi][ni], afr[mi],
                            bs[(ni & 1) * 2], bs[(ni & 1) * 2 + 1]);
                }
        }
        __syncthreads();
    }

    // ---------------- epilogue ----------------
    const int rg = lane >> 2;
    const int cg = (lane & 3) * 2;
#pragma unroll
    for (int mi = 0; mi < 4; mi++) {
#pragma unroll
        for (int ni = 0; ni < 8; ni++) {
            float* c = acc[mi][ni];
            int gr0 = m0 + wm * 64 + mi * 16 + rg;
            int gc  = n0 + wn * 64 + ni * 8 + cg;
            if (mode == 0) {
                float* C = (float*)out1;
                float b0 = bias ? bias[gc] : 0.0f;
                float b1 = bias ? bias[gc + 1] : 0.0f;
                *(float2*)(C + (size_t)gr0 * Nc + gc)       = {c[0] + b0, c[1] + b1};
                *(float2*)(C + (size_t)(gr0 + 8) * Nc + gc) = {c[2] + b0, c[3] + b1};
            } else if (mode == 1) {
                float gb = *gb_ptr;
                float* P = (float*)out1 + (size_t)blockIdx.z * cBatch;
                float* L = (float*)out2 + (size_t)blockIdx.z * cBatch;
                float l0 = c[0] * 0.0625f + gb, l1 = c[1] * 0.0625f + gb;
                float l2 = c[2] * 0.0625f + gb, l3 = c[3] * 0.0625f + gb;
                *(float2*)(L + (size_t)gr0 * Nc + gc)       = {l0, l1};
                *(float2*)(L + (size_t)(gr0 + 8) * Nc + gc) = {l2, l3};
                *(float2*)(P + (size_t)gr0 * Nc + gc)       =
                    {fast_sigmoid(l0), fast_sigmoid(l1)};
                *(float2*)(P + (size_t)(gr0 + 8) * Nc + gc) =
                    {fast_sigmoid(l2), fast_sigmoid(l3)};
            } else if (mode == 2) {  // fp16 output (hi only)
                ush* H = (ush*)out1;
                H[(size_t)gr0 * Nc + gc]           = f2h16(c[0]);
                H[(size_t)gr0 * Nc + gc + 1]       = f2h16(c[1]);
                H[(size_t)(gr0 + 8) * Nc + gc]     = f2h16(c[2]);
                H[(size_t)(gr0 + 8) * Nc + gc + 1] = f2h16(c[3]);
            } else if (mode == 3) {  // out_proj fused residual+transpose+fp16
                float* O = (float*)out1;
                ush*   H = (ush*)out2;
                int t0 = gr0 & 31, nn0 = gr0 >> 5;
                size_t d0 = ((size_t)t0 * NNODE + nn0) * Nc + gc;
                float v0 = c[0] + bias[gc]     + addrow[d0];
                float v1 = c[1] + bias[gc + 1] + addrow[d0 + 1];
                *(float2*)(O + d0) = {v0, v1};
                H[d0] = f2h16(v0); H[d0 + 1] = f2h16(v1);
                int t1 = (gr0 + 8) & 31, nn1 = (gr0 + 8) >> 5;
                size_t d1 = ((size_t)t1 * NNODE + nn1) * Nc + gc;
                float v2 = c[2] + bias[gc]     + addrow[d1];
                float v3 = c[3] + bias[gc + 1] + addrow[d1 + 1];
                *(float2*)(O + d1) = {v2, v3};
                H[d1] = f2h16(v2); H[d1 + 1] = f2h16(v3);
            } else {  // mode 4: + bias + cnt[row]*cvec[col]
                float* C = (float*)out1;
                float cn0 = (float)cntp[gr0];
                float cn1 = (float)cntp[gr0 + 8];
                float b0 = bias[gc]     + cn0 * addrow[gc];
                float b1 = bias[gc + 1] + cn0 * addrow[gc + 1];
                float b2 = bias[gc]     + cn1 * addrow[gc];
                float b3 = bias[gc + 1] + cn1 * addrow[gc + 1];
                *(float2*)(C + (size_t)gr0 * Nc + gc)       = {c[0] + b0, c[1] + b1};
                *(float2*)(C + (size_t)(gr0 + 8) * Nc + gc) = {c[2] + b2, c[3] + b3};
            }
        }
    }
}

// ===========================================================================
// Small SIMT SGEMM (exact fp32): C = A[M,K]@B[K,N] + bias
// ===========================================================================
__global__ void __launch_bounds__(256) sgemm_nn(
    const float* __restrict__ A, const float* __restrict__ B,
    const float* __restrict__ bias, float* __restrict__ C,
    int M, int Nc, int K)
{
    __shared__ float As[8][128];
    __shared__ float Bs[8][128];
    int tid = threadIdx.x;
    int bx = blockIdx.x, by = blockIdx.y;
    int tx = tid & 15, ty = tid >> 4;
    int arow = tid >> 1, acol = (tid & 1) * 4;
    int brow = tid >> 5, bcol = (tid & 31) * 4;
    const float* Ab = A + (size_t)by * 128 * K;
    const float* Bb = B + (size_t)bx * 128;
    float acc[8][8] = {};
    for (int k0 = 0; k0 < K; k0 += 8) {
        float4 av = *(const float4*)(Ab + (size_t)arow * K + k0 + acol);
        As[acol + 0][arow] = av.x; As[acol + 1][arow] = av.y;
        As[acol + 2][arow] = av.z; As[acol + 3][arow] = av.w;
        *(float4*)&Bs[brow][bcol] =
            *(const float4*)(Bb + (size_t)(k0 + brow) * Nc + bcol);
        __syncthreads();
#pragma unroll
        for (int kk = 0; kk < 8; kk++) {
            float4 a0 = *(float4*)&As[kk][ty * 8];
            float4 a1 = *(float4*)&As[kk][ty * 8 + 4];
            float4 b0 = *(float4*)&Bs[kk][tx * 8];
            float4 b1 = *(float4*)&Bs[kk][tx * 8 + 4];
            float ar[8] = {a0.x, a0.y, a0.z, a0.w, a1.x, a1.y, a1.z, a1.w};
            float br[8] = {b0.x, b0.y, b0.z, b0.w, b1.x, b1.y, b1.z, b1.w};
#pragma unroll
            for (int i = 0; i < 8; i++)
#pragma unroll
                for (int j = 0; j < 8; j++)
                    acc[i][j] = fmaf(ar[i], br[j], acc[i][j]);
        }
        __syncthreads();
    }
#pragma unroll
    for (int i = 0; i < 8; i++) {
        int r = by * 128 + ty * 8 + i;
#pragma unroll
        for (int j = 0; j < 8; j += 4) {
            int c = bx * 128 + tx * 8 + j;
            float4 v;
            v.x = acc[i][j] + bias[c];         v.y = acc[i][j + 1] + bias[c + 1];
            v.z = acc[i][j + 2] + bias[c + 2]; v.w = acc[i][j + 3] + bias[c + 3];
            *(float4*)(C + (size_t)r * Nc + c) = v;
        }
    }
}

// fold2: z=0 -> M1c = msg1_w @ W1bot; z=1 -> M2c = msg2_w @ W2bot  (256^3 each)
__global__ void __launch_bounds__(256) fold2_kernel(
    const float* __restrict__ m1w, const float* __restrict__ W1bot,
    const float* __restrict__ m2w, const float* __restrict__ W2bot)
{
    const float* A = blockIdx.z ? m2w : m1w;
    const float* B = blockIdx.z ? W2bot : W1bot;
    float* C = blockIdx.z ? g_M2c : g_M1c;
    __shared__ float As[8][128];
    __shared__ float Bs[8][128];
    int tid = threadIdx.x;
    int bx = blockIdx.x, by = blockIdx.y;
    int tx = tid & 15, ty = tid >> 4;
    int arow = tid >> 1, acol = (tid & 1) * 4;
    int brow = tid >> 5, bcol = (tid & 31) * 4;
    const float* Ab = A + (size_t)by * 128 * 256;
    const float* Bb = B + (size_t)bx * 128;
    float acc[8][8] = {};
    for (int k0 = 0; k0 < 256; k0 += 8) {
        float4 av = *(const float4*)(Ab + (size_t)arow * 256 + k0 + acol);
        As[acol + 0][arow] = av.x; As[acol + 1][arow] = av.y;
        As[acol + 2][arow] = av.z; As[acol + 3][arow] = av.w;
        *(float4*)&Bs[brow][bcol] =
            *(const float4*)(Bb + (size_t)(k0 + brow) * 256 + bcol);
        __syncthreads();
#pragma unroll
        for (int kk = 0; kk < 8; kk++) {
            float4 a0 = *(float4*)&As[kk][ty * 8];
            float4 a1 = *(float4*)&As[kk][ty * 8 + 4];
            float4 b0 = *(float4*)&Bs[kk][tx * 8];
            float4 b1 = *(float4*)&Bs[kk][tx * 8 + 4];
            float ar[8] = {a0.x, a0.y, a0.z, a0.w, a1.x, a1.y, a1.z, a1.w};
            float br[8] = {b0.x, b0.y, b0.z, b0.w, b1.x, b1.y, b1.z, b1.w};
#pragma unroll
            for (int i = 0; i < 8; i++)
#pragma unroll
                for (int j = 0; j < 8; j++)
                    acc[i][j] = fmaf(ar[i], br[j], acc[i][j]);
        }
        __syncthreads();
    }
#pragma unroll
    for (int i = 0; i < 8; i++) {
        int r = by * 128 + ty * 8 + i;
#pragma unroll
        for (int j = 0; j < 8; j += 4) {
            int c = bx * 128 + tx * 8 + j;
            float4 v = {acc[i][j], acc[i][j + 1], acc[i][j + 2], acc[i][j + 3]};
            *(float4*)(C + (size_t)r * 256 + c) = v;
        }
    }
}

// ===========================================================================
// Elementwise / helper kernels
// ===========================================================================
__global__ void pe_kernel() {
    int n = blockIdx.x;
    int i = threadIdx.x;  // 0..127
    float div = expf((float)(2 * i) * (-0.03597867333f));
    float ang = (float)n * div;
    g_pe[n * PDIM + 2 * i]     = sinf(ang);
    g_pe[n * PDIM + 2 * i + 1] = cosf(ang);
}

// cvec[h] = sum_k b[k] * Wbot[k*256+h]; grid (2,8), 8 threads per output
__global__ void cvec_kernel(const float* __restrict__ b1,
                            const float* __restrict__ W1bot,
                            const float* __restrict__ b2,
                            const float* __restrict__ W2bot)
{
    int h = blockIdx.y * 32 + (threadIdx.x >> 3);
    int l8 = threadIdx.x & 7;
    const float* b = blockIdx.x ? b2 : b1;
    const float* W = blockIdx.x ? W2bot : W1bot;
    float acc = 0.0f;
    for (int k = l8; k < 256; k += 8)
        acc = fmaf(b[k], W[k * 256 + h], acc);
#pragma unroll
    for (int o = 4; o > 0; o >>= 1)
        acc += __shfl_down_sync(0xffffffffu, acc, o);
    if (l8 == 0)
        (blockIdx.x ? g_cvec2 : g_cvec1)[h] = acc;
}

// ONE launch: all weight transposes (fp16 hi) + Wcat1/bias1 build.
__global__ void split_all(const float* __restrict__ upd2_w,
                          const float* __restrict__ in_w,
                          const float* __restrict__ out_w,
                          const float* __restrict__ q_w,
                          const float* __restrict__ k_w,
                          const float* __restrict__ upd1_w,
                          const float* __restrict__ upd1_b)
{
    int id = blockIdx.x * 256 + threadIdx.x;
    if (id < 65536) {
        int k = id >> 8, n = id & 255;                 // upd2top [256,256]
        g_wh[O_W2 + (size_t)n * 512 + k] = f2h16(upd2_w[id]);
    } else if (id < 131072) {
        int i = id - 65536;
        int k = i >> 8, n = i & 255;                   // M2c [256,256]
        g_wh[O_W2 + (size_t)n * 512 + 256 + k] = f2h16(g_M2c[i]);
    } else if (id < 393216) {
        int i = id - 131072;                           // in_w [256,1024]
        int k = i >> 10, n = i & 1023;
        g_wh[O_IN + (size_t)n * 256 + k] = f2h16(in_w[i]);
    } else if (id < 524288) {
        int i = id - 393216;                           // out_w [512,256]
        int k = i >> 8, n = i & 255;
        g_wh[O_OUT + (size_t)n * 512 + k] = f2h16(out_w[i]);
    } else if (id < 589824) {
        int i = id - 524288;                           // q_w [256,256] -> rows 0-255
        int k = i >> 8, n = i & 255;
        g_wh[O_QK + (size_t)n * 256 + k] = f2h16(q_w[i]);
    } else if (id < 655360) {
        int i = id - 589824;                           // k_w [256,256] -> rows 256-511
        int k = i >> 8, n = i & 255;
        g_wh[O_QK + (size_t)(n + 256) * 256 + k] = f2h16(k_w[i]);
    } else if (id < 786432) {
        int i = id - 655360;                           // Wcat1 [256,512]
        int k = i >> 9, n = i & 511;
        g_Wcat1[i] = (n < 256) ? upd1_w[k * 256 + n] : g_M1c[k * 256 + (n - 256)];
    } else if (id < 786944) {
        int n = id - 786432;
        g_bias1[n] = (n < 256) ? upd1_b[n] : 0.0f;
    }
}

// Build adjacency neighbor lists once; 4 rows per block for MLP
__global__ void build_nbr(const float* __restrict__ adj) {
    int base = blockIdx.x * 4;       // 4 consecutive flat rows (t*N + i)
    __shared__ int s_idx[4][NNODE];
    __shared__ int s_cnt[4];
    if (threadIdx.x < 4) s_cnt[threadIdx.x] = 0;
    __syncthreads();
    float4 v[4];
#pragma unroll
    for (int r = 0; r < 4; r++)
        v[r] = ((const float4*)(adj + (size_t)(base + r) * NNODE))[threadIdx.x];
    int j0 = threadIdx.x * 4;
#pragma unroll
    for (int r = 0; r < 4; r++) {
        if (v[r].x != 0.0f) s_idx[r][atomicAdd(&s_cnt[r], 1)] = j0;
        if (v[r].y != 0.0f) s_idx[r][atomicAdd(&s_cnt[r], 1)] = j0 + 1;
        if (v[r].z != 0.0f) s_idx[r][atomicAdd(&s_cnt[r], 1)] = j0 + 2;
        if (v[r].w != 0.0f) s_idx[r][atomicAdd(&s_cnt[r], 1)] = j0 + 3;
    }
    __syncthreads();
#pragma unroll
    for (int r = 0; r < 4; r++) {
        size_t row = base + r;
        int cnt = s_cnt[r];
        if (threadIdx.x == 0) g_ncnt[row] = cnt;
        for (int p = threadIdx.x; p < cnt; p += 256)
            g_nidx[row * NNODE + p] = s_idx[r][p];
    }
}

// Layer-1 FUSED: gather(precat hi-half) + precat lo-half + cnt*cvec1
// + relu + LN -> g_x fp32 and fp16 split into c1h/c1l cols [0,256)
__global__ void gather1_fused(const float* __restrict__ gam,
                              const float* __restrict__ bet)
{
    int i = blockIdx.x, t = blockIdx.y;
    size_t row = (size_t)t * NNODE + i;
    int cnt = g_ncnt[row];
    const int* idx = g_nidx + row * NNODE;
    int h = threadIdx.x;
    float acc = g_precat[(size_t)i * 512 + h] + (float)cnt * g_cvec1[h];
    for (int p = 0; p < cnt; p++)
        acc += g_precat[(size_t)idx[p] * 512 + 256 + h];
    float v = fmaxf(acc, 0.0f);
    float s = v, q = v * v;
#pragma unroll
    for (int o = 16; o > 0; o >>= 1) {
        s += __shfl_xor_sync(0xffffffffu, s, o);
        q += __shfl_xor_sync(0xffffffffu, q, o);
    }
    __shared__ float ss[8], qq[8];
    __shared__ float s_mu, s_rstd;
    int w = h >> 5;
    if ((h & 31) == 0) { ss[w] = s; qq[w] = q; }
    __syncthreads();
    if (h == 0) {
        float S = 0, QQ = 0;
        for (int j = 0; j < 8; j++) { S += ss[j]; QQ += qq[j]; }
        float mu = S * (1.0f / 256.0f);
        float var = QQ * (1.0f / 256.0f) - mu * mu;
        s_mu = mu; s_rstd = rsqrtf(var + 1e-5f);
    }
    __syncthreads();
    float o = (v - s_mu) * s_rstd * gam[h] + bet[h];
    g_x[row * HDIM + h] = o;
    ush hh, ll; fsplit16(o, hh, ll);
    g_c1h[row * 512 + h] = hh;
    g_c1l[row * 512 + h] = ll;
}

// Layer-2 gather of x (per-t), fp16 split into c1h/c1l cols [256,512)
__global__ void gather2(void) {
    int i = blockIdx.x, t = blockIdx.y;
    size_t row = (size_t)t * NNODE + i;
    int cnt = g_ncnt[row];
    const int* idx = g_nidx + row * NNODE;
    int h = threadIdx.x;
    const float* mb = g_x + (size_t)t * NNODE * HDIM;
    float acc = 0.0f;
    for (int p = 0; p < cnt; p++)
        acc += mb[(size_t)idx[p] * HDIM + h];
    ush hi, lo; fsplit16(acc, hi, lo);
    g_c1h[row * 512 + 256 + h] = hi;
    g_c1l[row * 512 + 256 + h] = lo;
}

// FUSED: relu+LN2 (writes x2 fp32, t-major) then Mamba pre-LN of the result
// (writes fp16 splits xh/xl, n-major). In-place on g_x2.
__global__ void ln2_mamba(const float* __restrict__ g2, const float* __restrict__ b2,
                          const float* __restrict__ gm, const float* __restrict__ bm)
{
    int rin = blockIdx.x;              // t*N + n
    int tid = threadIdx.x;
    int t = rin >> 10, n = rin & 1023;
    __shared__ float ss[8], qq[8];
    __shared__ float s_mu, s_rstd;
    int w = tid >> 5;

    float v = fmaxf(g_x2[(size_t)rin * HDIM + tid], 0.0f);
    float s = v, q = v * v;
#pragma unroll
    for (int o = 16; o > 0; o >>= 1) {
        s += __shfl_xor_sync(0xffffffffu, s, o);
        q += __shfl_xor_sync(0xffffffffu, q, o);
    }
    if ((tid & 31) == 0) { ss[w] = s; qq[w] = q; }
    __syncthreads();
    if (tid == 0) {
        float S = 0, QQ = 0;
        for (int i = 0; i < 8; i++) { S += ss[i]; QQ += qq[i]; }
        float mu = S * (1.0f / 256.0f);
        float var = QQ * (1.0f / 256.0f) - mu * mu;
        s_mu = mu; s_rstd = rsqrtf(var + 1e-5f);
    }
    __syncthreads();
    float o = (v - s_mu) * s_rstd * g2[tid] + b2[tid];
    g_x2[(size_t)rin * HDIM + tid] = o;
    __syncthreads();

    float s2 = o, q2 = o * o;
#pragma unroll
    for (int of = 16; of > 0; of >>= 1) {
        s2 += __shfl_xor_sync(0xffffffffu, s2, of);
        q2 += __shfl_xor_sync(0xffffffffu, q2, of);
    }
    if ((tid & 31) == 0) { ss[w] = s2; qq[w] = q2; }
    __syncthreads();
    if (tid == 0) {
        float S = 0, QQ = 0;
        for (int i = 0; i < 8; i++) { S += ss[i]; QQ += qq[i]; }
        float mu = S * (1.0f / 256.0f);
        float var = QQ * (1.0f / 256.0f) - mu * mu;
        s_mu = mu; s_rstd = rsqrtf(var + 1e-5f);
    }
    __syncthreads();
    float o2 = (o - s_mu) * s_rstd * gm[tid] + bm[tid];
    size_t dst = ((size_t)n * TSTEP + t) * HDIM + tid;
    ush h, l; fsplit16(o2, h, l);
    g_xh[dst] = h; g_xl[dst] = l;
}

__global__ void transpose_w3(const float* __restrict__ dw,
                             const float* __restrict__ bw,
                             const float* __restrict__ cw)
{
    int id = blockIdx.x * 256 + threadIdx.x;  // 8192
    if (id < EDIM * DTR) {
        int k = id >> 4, n = id & 15;
        g_dwT[n * EDIM + k] = dw[id];
        g_bwT[n * EDIM + k] = bw[id];
        g_cwT[n * EDIM + k] = cw[id];
    }
}

// proj3 with inline silu on xp
__global__ void proj3_kernel(const float* __restrict__ db,
                             const float* __restrict__ bb,
                             const float* __restrict__ cb)
{
    int r = blockIdx.x * 16 + (threadIdx.x >> 4);
    int n = threadIdx.x & 15;
    const float4* a4 = (const float4*)(g_xp + (size_t)r * 1024);
    const float4* d4 = (const float4*)(g_dwT + n * EDIM);
    const float4* b4 = (const float4*)(g_bwT + n * EDIM);
    const float4* c4 = (const float4*)(g_cwT + n * EDIM);
    float ad = 0, ab = 0, ac = 0;
#pragma unroll 4
    for (int k = 0; k < EDIM / 4; k++) {
        float4 a = a4[k];
        a.x *= fast_sigmoid(a.x); a.y *= fast_sigmoid(a.y);
        a.z *= fast_sigmoid(a.z); a.w *= fast_sigmoid(a.w);
        float4 d = d4[k], b = b4[k], c = c4[k];
        ad = fmaf(a.x, d.x, fmaf(a.y, d.y, fmaf(a.z, d.z, fmaf(a.w, d.w, ad))));
        ab = fmaf(a.x, b.x, fmaf(a.y, b.y, fmaf(a.z, b.z, fmaf(a.w, b.w, ab))));
        ac = fmaf(a.x, c.x, fmaf(a.y, c.y, fmaf(a.z, c.z, fmaf(a.w, c.w, ac))));
    }
    size_t o = (size_t)r * 16 + n;
    g_d1[o] = ad + db[n];
    g_Bm[o] = ab + bb[n];
    g_Cm[o] = ac + cb[n];
}

// Selective scan with fused delta computation and inline silu on xp;
// writes y as fp16 splits into g_c1h/g_c1l
__global__ void __launch_bounds__(512) scan_kernel(
    const float* __restrict__ A_log, const float* __restrict__ D_vec,
    const float* __restrict__ dtw, const float* __restrict__ dtb)
{
    int n = blockIdx.x;
    int e = threadIdx.x;
    float A[SDIM], h[SDIM], wreg[DTR];
#pragma unroll
    for (int s = 0; s < SDIM; s++) {
        A[s] = -fast_exp(A_log[e * SDIM + s]);
        h[s] = 0.0f;
    }
#pragma unroll
    for (int k = 0; k < DTR; k++)
        wreg[k] = dtw[k * EDIM + e];
    float dbv = dtb[e];
    float Dv = D_vec[e];
    __shared__ float sbv[TSTEP * SDIM], scv[TSTEP * SDIM], sd1[TSTEP * DTR];
    sbv[e] = g_Bm[(size_t)n * (TSTEP * SDIM) + e];
    scv[e] = g_Cm[(size_t)n * (TSTEP * SDIM) + e];
    sd1[e] = g_d1[(size_t)n * (TSTEP * DTR) + e];
    __syncthreads();
    for (int t = 0; t < TSTEP; t++) {
        size_t r = (size_t)n * TSTEP + t;
        const float* sb = sbv + t * SDIM;
        const float* sc = scv + t * SDIM;
        const float* d1 = sd1 + t * DTR;
        float dacc = dbv;
#pragma unroll
        for (int k = 0; k < DTR; k++)
            dacc = fmaf(d1[k], wreg[k], dacc);
        float dt = fast_softplus(dacc);
        float xv = g_xp[r * 1024 + e];
        float xt = xv * fast_sigmoid(xv);
        float dx = dt * xt;
        float yv = 0.0f;
#pragma unroll
        for (int s = 0; s < SDIM; s++) {
            h[s] = fmaf(fast_exp(dt * A[s]), h[s], dx * sb[s]);
            yv   = fmaf(sc[s], h[s], yv);
        }
        yv += xt * Dv;
        float g = g_xp[r * 1024 + EDIM + e];
        yv *= g * fast_sigmoid(g);
        ush hi, lo; fsplit16(yv, hi, lo);
        g_c1h[r * EDIM + e] = hi;
        g_c1l[r * EDIM + e] = lo;
    }
}

// ===========================================================================
// Host launch
// ===========================================================================
#define GEMM_SMEM 65536

extern "C" void kernel_launch(void* const* d_in, const int* in_sizes, int n_in,
                              void* d_out, int out_size)
{
    const float* adj     = (const float*)d_in[0];
    const float* msg1_w  = (const float*)d_in[1];
    const float* msg1_b  = (const float*)d_in[2];
    const float* upd1_w  = (const float*)d_in[3];
    const float* upd1_b  = (const float*)d_in[4];
    const float* ln1_g   = (const float*)d_in[5];
    const float* ln1_b   = (const float*)d_in[6];
    const float* msg2_w  = (const float*)d_in[7];
    const float* msg2_b  = (const float*)d_in[8];
    const float* upd2_w  = (const float*)d_in[9];
    const float* upd2_b  = (const float*)d_in[10];
    const float* ln2_g   = (const float*)d_in[11];
    const float* ln2_b   = (const float*)d_in[12];
    const float* mbln_g  = (const float*)d_in[13];
    const float* mbln_b  = (const float*)d_in[14];
    const float* in_w    = (const float*)d_in[15];
    const float* in_b    = (const float*)d_in[16];
    const float* delta_w = (const float*)d_in[17];
    const float* delta_b = (const float*)d_in[18];
    const float* dt_w    = (const float*)d_in[19];
    const float* dt_b    = (const float*)d_in[20];
    const float* Bp_w    = (const float*)d_in[21];
    const float* Bp_b    = (const float*)d_in[22];
    const float* Cp_w    = (const float*)d_in[23];
    const float* Cp_b    = (const float*)d_in[24];
    const float* A_log   = (const float*)d_in[25];
    const float* D_vec   = (const float*)d_in[26];
    const float* out_w   = (const float*)d_in[27];
    const float* out_b   = (const float*)d_in[28];
    const float* q_w     = (const float*)d_in[29];
    const float* k_w     = (const float*)d_in[30];
    const float* gate_b  = (const float*)d_in[31];

    float* out    = (float*)d_out;
    float* outs   = out;                                    // [T,N,H]
    float* probs  = out + (size_t)TSTEP * NNODE * HDIM;     // [T,N,N]
    float* logits = probs + (size_t)TSTEP * NNODE * NNODE;  // [T,N,N]

    cudaFuncSetAttribute(gemm_k, cudaFuncAttributeMaxDynamicSharedMemorySize,
                         GEMM_SMEM);

    float *pe_, *Wcat1_, *bias1_, *cvec2_, *precat_, *x2_, *xp_;
    int* cnt_;
    ush *c1h_, *c1l_, *xh_, *xl_, *wh_;
    cudaGetSymbolAddress((void**)&pe_,     g_pe);
    cudaGetSymbolAddress((void**)&Wcat1_,  g_Wcat1);
    cudaGetSymbolAddress((void**)&bias1_,  g_bias1);
    cudaGetSymbolAddress((void**)&cvec2_,  g_cvec2);
    cudaGetSymbolAddress((void**)&precat_, g_precat);
    cudaGetSymbolAddress((void**)&x2_,     g_x2);
    cudaGetSymbolAddress((void**)&xp_,     g_xp);
    cudaGetSymbolAddress((void**)&cnt_,    g_ncnt);
    cudaGetSymbolAddress((void**)&c1h_,    g_c1h);
    cudaGetSymbolAddress((void**)&c1l_,    g_c1l);
    cudaGetSymbolAddress((void**)&xh_,     g_xh);
    cudaGetSymbolAddress((void**)&xl_,     g_xl);
    cudaGetSymbolAddress((void**)&wh_,     g_wh);

    const float* W1bot = upd1_w + 256 * 256;
    const float* W2bot = upd2_w + 256 * 256;

    // 1. prologue
    pe_kernel<<<NNODE, 128>>>();
    build_nbr<<<NT / 4, 256>>>(adj);
    fold2_kernel<<<dim3(2, 2, 2), 256>>>(msg1_w, W1bot, msg2_w, W2bot);
    cvec_kernel<<<dim3(2, 8), 256>>>(msg1_b, W1bot, msg2_b, W2bot);
    split_all<<<3074, 256>>>(upd2_w, in_w, out_w, q_w, k_w, upd1_w, upd1_b);
    sgemm_nn<<<dim3(4, 8), 256>>>(pe_, Wcat1_, bias1_, precat_, NNODE, 512, 256);
    // 2. layer 1: fused gather+relu+LN (no NT GEMM)
    gather1_fused<<<dim3(NNODE, TSTEP), 256>>>(ln1_g, ln1_b);
    // 3. layer 2: gather x; combined [x|aggx] @ [W2top; M2c] GEMM
    //    (fp16 2-pass, mode 4)
    gather2<<<dim3(NNODE, TSTEP), 256>>>();
    gemm_k<<<dim3(2, NT / 128), 128, GEMM_SMEM>>>(
        c1h_, c1l_, wh_ + O_W2, upd2_b, cvec2_, cnt_, x2_,
        nullptr, nullptr, 512, 256, 4, 2, 512, 512, 0, 0, 0);
    // 4. fused relu+LN2 + mamba pre-LN; then in_proj GEMM (fp16 2-pass)
    ln2_mamba<<<NT, 256>>>(ln2_g, ln2_b, mbln_g, mbln_b);
    gemm_k<<<dim3(8, NT / 128), 128, GEMM_SMEM>>>(
        xh_, xl_, wh_ + O_IN, in_b, nullptr, nullptr, xp_,
        nullptr, nullptr, 256, 1024, 0, 2, 256, 256, 0, 0, 0);
    // 5. small projections (inline silu)
    transpose_w3<<<(EDIM * DTR + 255) / 256, 256>>>(delta_w, Bp_w, Cp_w);
    proj3_kernel<<<NT / 16, 256>>>(delta_b, Bp_b, Cp_b);
    // 6. scan (fused delta + silu; writes y fp16 splits into c1h/c1l)
    scan_kernel<<<NNODE, EDIM>>>(A_log, D_vec, dt_w, dt_b);
    // 7. out projection (fp16 2-pass) with fused residual+transpose epilogue
    gemm_k<<<dim3(2, NT / 128), 128, GEMM_SMEM>>>(
        c1h_, c1l_, wh_ + O_OUT, out_b, x2_, nullptr, outs, xh_,
        nullptr, 512, 256, 3, 2, 512, 512, 0, 0, 0);
    // 8. merged q+k GEMM (fp16 1-pass) into qk buffer (c1h reused, [NT,512]),
    //    then score head: A = qk[:,0:256], B = qk[:,256:512] (strided)
    gemm_k<<<dim3(4, NT / 128), 128, GEMM_SMEM>>>(
        xh_, nullptr, wh_ + O_QK, nullptr, nullptr, nullptr, c1h_,
        nullptr, nullptr, 256, 512, 2, 1, 256, 256, 0, 0, 0);
    gemm_k<<<dim3(8, 8, TSTEP), 128, GEMM_SMEM>>>(
        c1h_, nullptr, c1h_ + 256, nullptr, nullptr, nullptr,
        probs, logits, gate_b, 256, 1024, 1, 1, 512, 512,
        (size_t)NNODE * 512, (size_t)NNODE * 512, (size_t)NNODE * NNODE);
}